// round 1
// baseline (speedup 1.0000x reference)
#include <cuda_runtime.h>
#include <math.h>
#include <stdint.h>

// ---------------------------------------------------------------------------
// Problem constants
// ---------------------------------------------------------------------------
#define B    64
#define T    32      // == SEG
#define D    4096
#define C    50
#define A_   300
#define H    256     // GRU hidden per direction
#define GI_W 1536    // 2 * 3H / ... (768 fwd + 768 bwd)

// ---------------------------------------------------------------------------
// Scratch (static device globals; no allocation allowed)
// ---------------------------------------------------------------------------
__device__ float g_valid[B * T * D];        // 33.5 MB
__device__ float g_GI[B * T * GI_W];        // 12.6 MB   [b][s][1536]
__device__ float g_feats[B * T * 512];      // 4.2 MB    [b][s][512]
__device__ float g_attr1[C * 4096];         // 0.82 MB
__device__ float g_attr2[C * 512];
__device__ float g_logits[B * C * T];       // [row=b*C+c][s]
__device__ float g_cmax[T];
__device__ float g_csum[T];
__device__ float g_hbuf[2 * 2 * B * H];     // [phase][dir][b][i]
__device__ int          g_bar_count;
__device__ unsigned int g_bar_gen;

// ---------------------------------------------------------------------------
// 1) Segment selection: per-sample mean threshold, stable compaction, zero-pad
// ---------------------------------------------------------------------------
__global__ __launch_bounds__(256) void select_kernel(
    const float* __restrict__ bf,    // [B,T,D]
    const float* __restrict__ att,   // [B,T]
    float* __restrict__ valid)       // [B,T,D]
{
    int b = blockIdx.x;
    __shared__ float attS[T];
    __shared__ int   order[T];
    __shared__ int   cnt;
    int tid = threadIdx.x;

    if (tid < T) attS[tid] = att[b * T + tid];
    __syncthreads();
    if (tid == 0) {
        float s = 0.f;
        for (int t = 0; t < T; t++) s += attS[t];
        float thr = s / (float)T;
        int idx = 0;
        for (int t = 0; t < T; t++) if (attS[t] >= thr) order[idx++] = t;
        cnt = idx;
        for (int t = 0; t < T; t++) if (attS[t] <  thr) order[idx++] = t;
    }
    __syncthreads();

    for (int s = 0; s < T; s++) {
        const float4* src = (const float4*)(bf + ((size_t)b * T + order[s]) * D);
        float4*       dst = (float4*)(valid + ((size_t)b * T + s) * D);
        bool keep = (s < cnt);
        for (int t = tid; t < D / 4; t += 256)
            dst[t] = keep ? src[t] : make_float4(0.f, 0.f, 0.f, 0.f);
    }
}

// ---------------------------------------------------------------------------
// 2) Generic tiled fp32 GEMM:  C[M,N] = A[M,K] * W[N,K]^T + bias[N]  (opt relu)
//    block tile 64x64, BK=16, 256 threads, 4x4 per thread
// ---------------------------------------------------------------------------
template <bool RELU>
__global__ __launch_bounds__(256) void gemm_tn(
    const float* __restrict__ Ag, int lda,
    const float* __restrict__ Wg, int ldw,
    const float* __restrict__ bias,
    float* __restrict__ Cg, int ldc,
    int M, int N, int K)
{
    __shared__ float As[16][65];
    __shared__ float Ws[16][65];
    int tid  = threadIdx.x;
    int row0 = blockIdx.y * 64;
    int col0 = blockIdx.x * 64;
    int lm = tid >> 2;            // 0..63
    int lk = (tid & 3) * 4;       // 0,4,8,12
    int ty = tid >> 4;            // 0..15
    int tx = tid & 15;            // 0..15
    float acc[4][4];
#pragma unroll
    for (int i = 0; i < 4; i++)
#pragma unroll
        for (int j = 0; j < 4; j++) acc[i][j] = 0.f;

    for (int k0 = 0; k0 < K; k0 += 16) {
        int r = row0 + lm;
        int c = col0 + lm;
#pragma unroll
        for (int i = 0; i < 4; i++) {
            int k = k0 + lk + i;
            As[lk + i][lm] = (r < M && k < K) ? Ag[(size_t)r * lda + k] : 0.f;
            Ws[lk + i][lm] = (c < N && k < K) ? Wg[(size_t)c * ldw + k] : 0.f;
        }
        __syncthreads();
#pragma unroll
        for (int kk = 0; kk < 16; kk++) {
            float a[4], w[4];
#pragma unroll
            for (int i = 0; i < 4; i++) a[i] = As[kk][ty + 16 * i];
#pragma unroll
            for (int j = 0; j < 4; j++) w[j] = Ws[kk][tx + 16 * j];
#pragma unroll
            for (int i = 0; i < 4; i++)
#pragma unroll
                for (int j = 0; j < 4; j++)
                    acc[i][j] = fmaf(a[i], w[j], acc[i][j]);
        }
        __syncthreads();
    }

#pragma unroll
    for (int i = 0; i < 4; i++) {
        int r = row0 + ty + 16 * i;
        if (r >= M) continue;
#pragma unroll
        for (int j = 0; j < 4; j++) {
            int c = col0 + tx + 16 * j;
            if (c >= N) continue;
            float v = acc[i][j] + bias[c];
            if (RELU) v = fmaxf(v, 0.f);
            Cg[(size_t)r * ldc + c] = v;
        }
    }
}

// ---------------------------------------------------------------------------
// 3) GRU recurrence — persistent kernel, software grid barrier, 128 blocks.
//    block = (dir, 4-hidden-unit chunk); thread = (batch, unit-in-chunk).
//    whh rows cached in smem ONCE for all 32 steps; h exchanged via global
//    double buffer.
// ---------------------------------------------------------------------------
#define GRU_BLOCKS 128

__device__ __forceinline__ void grid_barrier()
{
    __syncthreads();
    __threadfence();
    if (threadIdx.x == 0) {
        unsigned int g = *(volatile unsigned int*)&g_bar_gen;
        int t = atomicAdd(&g_bar_count, 1);
        if (t == GRU_BLOCKS - 1) {
            g_bar_count = 0;
            __threadfence();
            atomicExch(&g_bar_gen, g + 1);
        } else {
            while (*(volatile unsigned int*)&g_bar_gen == g) { __nanosleep(32); }
        }
    }
    __syncthreads();
    __threadfence();
}

__global__ __launch_bounds__(256) void gru_kernel(
    const float* __restrict__ GI,      // [b][s][1536]
    const float* __restrict__ whh_f,   // [768,256]
    const float* __restrict__ whh_b,
    const float* __restrict__ bhh_f,   // [768]
    const float* __restrict__ bhh_b,
    float* __restrict__ feats)         // [b][s][512]
{
    extern __shared__ float4 sm4[];
    float4* sW4 = sm4;                 // [12][65]  gate rows (r,z,n) x 4 units
    float4* hS4 = sm4 + 12 * 65;       // [64][65]  h for all batches of this dir

    int d  = blockIdx.x >> 6;          // direction
    int hc = blockIdx.x & 63;          // hidden chunk (4 units)
    int tid = threadIdx.x;
    int b = tid >> 2;                  // 0..63
    int u = tid & 3;                   // 0..3
    int i = hc * 4 + u;                // hidden unit 0..255

    const float* whh = d ? whh_b : whh_f;
    const float* bhh = d ? bhh_b : bhh_f;

    // load the 12 whh rows this block ever needs (once)
    for (int t = tid; t < 12 * 64; t += 256) {
        int rr = t >> 6;               // 0..11  (gate*4 + unit)
        int k4 = t & 63;
        int g  = rr >> 2, uu = rr & 3;
        int row = g * H + hc * 4 + uu;
        sW4[rr * 65 + k4] = ((const float4*)(whh + (size_t)row * H))[k4];
    }
    float br = bhh[i], bz = bhh[H + i], bn = bhh[2 * H + i];

    float h = 0.f;
    g_hbuf[d * (B * H) + b * H + i] = 0.f;   // phase 0 init
    grid_barrier();

    for (int t = 0; t < T; t++) {
        int p = t & 1;
        // stage full h[dir] into smem
        const float4* hp4 = (const float4*)(g_hbuf + p * (2 * B * H) + d * (B * H));
        for (int idx = tid; idx < B * (H / 4); idx += 256)
            hS4[(idx >> 6) * 65 + (idx & 63)] = hp4[idx];
        __syncthreads();

        const float4* hb = &hS4[b * 65];
        const float4* wr = &sW4[(0 + u) * 65];
        const float4* wz = &sW4[(4 + u) * 65];
        const float4* wn = &sW4[(8 + u) * 65];
        float ar = 0.f, az = 0.f, an = 0.f;
#pragma unroll 16
        for (int k4 = 0; k4 < 64; k4++) {
            float4 hv = hb[k4];
            float4 a  = wr[k4];
            ar = fmaf(hv.x, a.x, fmaf(hv.y, a.y, fmaf(hv.z, a.z, fmaf(hv.w, a.w, ar))));
            float4 zz = wz[k4];
            az = fmaf(hv.x, zz.x, fmaf(hv.y, zz.y, fmaf(hv.z, zz.z, fmaf(hv.w, zz.w, az))));
            float4 nn = wn[k4];
            an = fmaf(hv.x, nn.x, fmaf(hv.y, nn.y, fmaf(hv.z, nn.z, fmaf(hv.w, nn.w, an))));
        }

        int s = d ? (T - 1 - t) : t;
        const float* gi = GI + ((size_t)b * T + s) * GI_W + d * 768;
        float ir  = gi[i];
        float iz  = gi[H + i];
        float in_ = gi[2 * H + i];

        float r = 1.f / (1.f + expf(-(ir + ar + br)));
        float z = 1.f / (1.f + expf(-(iz + az + bz)));
        float n = tanhf(in_ + r * (an + bn));
        h = (1.f - z) * n + z * h;

        feats[((size_t)b * T + s) * 512 + d * H + i] = h;
        g_hbuf[(p ^ 1) * (2 * B * H) + d * (B * H) + b * H + i] = h;

        grid_barrier();
    }
}

// ---------------------------------------------------------------------------
// 4) Fused relation head: one block per (c,b) pair.
//    d[s][k]=(feats-attr)^2 computed on the fly; 32x256x512 GEMM; relu;
//    fc4 dot -> logits[b*C+c][s]. Never materializes diff2.
// ---------------------------------------------------------------------------
__global__ __launch_bounds__(256) void relation_kernel(
    const float* __restrict__ feats,   // [B,T,512]
    const float* __restrict__ attr2,   // [C,512]
    const float* __restrict__ w3,      // [256,512]
    const float* __restrict__ b3,      // [256]
    const float* __restrict__ w4,      // [256]
    const float* __restrict__ b4,      // [1]
    float* __restrict__ logits)        // [B*C, T]
{
    int c = blockIdx.x;   // 0..49
    int b = blockIdx.y;   // 0..63
    int tid = threadIdx.x;
    __shared__ float aS[512];
    __shared__ float dS[32][17];
    __shared__ float wS[16][260];
    __shared__ float part[32][33];

    for (int t = tid; t < 512; t += 256) aS[t] = attr2[(size_t)c * 512 + t];

    int ts = tid >> 5;    // 0..7 : owns s = ts + 8*i
    int tj = tid & 31;    // 0..31: owns j = tj + 32*m
    float acc[4][8];
#pragma unroll
    for (int i = 0; i < 4; i++)
#pragma unroll
        for (int m = 0; m < 8; m++) acc[i][m] = 0.f;
    __syncthreads();

    for (int k0 = 0; k0 < 512; k0 += 16) {
        // W3 tile: thread tid owns row j=tid, 16 k as 4 float4s
        const float4* wrow = (const float4*)(w3 + (size_t)tid * 512 + k0);
        float4 v0 = wrow[0], v1 = wrow[1], v2 = wrow[2], v3 = wrow[3];
        wS[0][tid] = v0.x;  wS[1][tid] = v0.y;  wS[2][tid] = v0.z;  wS[3][tid] = v0.w;
        wS[4][tid] = v1.x;  wS[5][tid] = v1.y;  wS[6][tid] = v1.z;  wS[7][tid] = v1.w;
        wS[8][tid] = v2.x;  wS[9][tid] = v2.y;  wS[10][tid] = v2.z; wS[11][tid] = v2.w;
        wS[12][tid] = v3.x; wS[13][tid] = v3.y; wS[14][tid] = v3.z; wS[15][tid] = v3.w;
        // diff^2 tile
        if (tid < 128) {
            int s  = tid >> 2;
            int kq = (tid & 3) * 4;
            float4 f = *(const float4*)(feats + ((size_t)b * T + s) * 512 + k0 + kq);
            float d0 = f.x - aS[k0 + kq + 0];
            float d1 = f.y - aS[k0 + kq + 1];
            float d2 = f.z - aS[k0 + kq + 2];
            float d3 = f.w - aS[k0 + kq + 3];
            dS[s][kq + 0] = d0 * d0;
            dS[s][kq + 1] = d1 * d1;
            dS[s][kq + 2] = d2 * d2;
            dS[s][kq + 3] = d3 * d3;
        }
        __syncthreads();
#pragma unroll
        for (int kk = 0; kk < 16; kk++) {
            float a[4], w[8];
#pragma unroll
            for (int i = 0; i < 4; i++) a[i] = dS[ts + 8 * i][kk];
#pragma unroll
            for (int m = 0; m < 8; m++) w[m] = wS[kk][tj + 32 * m];
#pragma unroll
            for (int i = 0; i < 4; i++)
#pragma unroll
                for (int m = 0; m < 8; m++)
                    acc[i][m] = fmaf(a[i], w[m], acc[i][m]);
        }
        __syncthreads();
    }

    // relu + fc4 dot (per-thread partial over its 8 j-columns)
#pragma unroll
    for (int i = 0; i < 4; i++) {
        float p = 0.f;
#pragma unroll
        for (int m = 0; m < 8; m++) {
            int j = tj + 32 * m;
            float hh = fmaxf(acc[i][m] + b3[j], 0.f);
            p = fmaf(hh, w4[j], p);
        }
        part[ts + 8 * i][tj] = p;
    }
    __syncthreads();
    if (tid < 32) {
        float s = b4[0];
        for (int t2 = 0; t2 < 32; t2++) s += part[tid][t2];
        logits[((size_t)b * C + c) * T + tid] = s;
    }
}

// ---------------------------------------------------------------------------
// 5) Softmax over dim-0 (3200) per segment column, then mean over columns
// ---------------------------------------------------------------------------
__global__ __launch_bounds__(256) void softmax_colreduce(
    const float* __restrict__ logits, float* __restrict__ cmax, float* __restrict__ csum)
{
    int t = blockIdx.x;   // column 0..31
    int tid = threadIdx.x;
    __shared__ float red[256];
    float m = -1e30f;
    for (int i = tid; i < B * C; i += 256) m = fmaxf(m, logits[(size_t)i * T + t]);
    red[tid] = m; __syncthreads();
    for (int s = 128; s > 0; s >>= 1) {
        if (tid < s) red[tid] = fmaxf(red[tid], red[tid + s]);
        __syncthreads();
    }
    float mx = red[0];
    __syncthreads();
    float sum = 0.f;
    for (int i = tid; i < B * C; i += 256) sum += expf(logits[(size_t)i * T + t] - mx);
    red[tid] = sum; __syncthreads();
    for (int s = 128; s > 0; s >>= 1) {
        if (tid < s) red[tid] += red[tid + s];
        __syncthreads();
    }
    if (tid == 0) { cmax[t] = mx; csum[t] = red[0]; }
}

__global__ __launch_bounds__(256) void softmax_out(
    const float* __restrict__ logits, const float* __restrict__ cmax,
    const float* __restrict__ csum, float* __restrict__ out)
{
    __shared__ float mS[T], sS[T];
    int tid = threadIdx.x;
    if (tid < T) { mS[tid] = cmax[tid]; sS[tid] = csum[tid]; }
    __syncthreads();
    int i = blockIdx.x * 256 + tid;
    if (i < B * C) {
        float a = 0.f;
        const float* row = logits + (size_t)i * T;
#pragma unroll
        for (int t = 0; t < T; t++) a += expf(row[t] - mS[t]) / sS[t];
        out[i] = a * (1.f / (float)T);
    }
}

// ---------------------------------------------------------------------------
// Launch
// ---------------------------------------------------------------------------
extern "C" void kernel_launch(void* const* d_in, const int* in_sizes, int n_in,
                              void* d_out, int out_size)
{
    const float* batch_features  = (const float*)d_in[0];
    const float* batch_att       = (const float*)d_in[1];
    const float* batch_attrs     = (const float*)d_in[2];
    const float* fc1_w = (const float*)d_in[3];
    const float* fc1_b = (const float*)d_in[4];
    const float* fc2_w = (const float*)d_in[5];
    const float* fc2_b = (const float*)d_in[6];
    const float* fc3_w = (const float*)d_in[7];
    const float* fc3_b = (const float*)d_in[8];
    const float* fc4_w = (const float*)d_in[9];
    const float* fc4_b = (const float*)d_in[10];
    const float* gru_wih_f = (const float*)d_in[11];
    const float* gru_whh_f = (const float*)d_in[12];
    const float* gru_bih_f = (const float*)d_in[13];
    const float* gru_bhh_f = (const float*)d_in[14];
    const float* gru_wih_b = (const float*)d_in[15];
    const float* gru_whh_b = (const float*)d_in[16];
    const float* gru_bih_b = (const float*)d_in[17];
    const float* gru_bhh_b = (const float*)d_in[18];
    float* out = (float*)d_out;

    float* valid;  cudaGetSymbolAddress((void**)&valid,  g_valid);
    float* GI;     cudaGetSymbolAddress((void**)&GI,     g_GI);
    float* feats;  cudaGetSymbolAddress((void**)&feats,  g_feats);
    float* attr1;  cudaGetSymbolAddress((void**)&attr1,  g_attr1);
    float* attr2;  cudaGetSymbolAddress((void**)&attr2,  g_attr2);
    float* logits; cudaGetSymbolAddress((void**)&logits, g_logits);
    float* cmax;   cudaGetSymbolAddress((void**)&cmax,   g_cmax);
    float* csum;   cudaGetSymbolAddress((void**)&csum,   g_csum);

    // 1) segment selection
    select_kernel<<<B, 256>>>(batch_features, batch_att, valid);

    // 2) GRU input projection GEMMs: [2048,4096] x [768,4096]^T (x2 dirs)
    {
        dim3 grid(768 / 64, (B * T) / 64);
        gemm_tn<false><<<grid, 256>>>(valid, D, gru_wih_f, D, gru_bih_f,
                                      GI + 0,   GI_W, B * T, 768, D);
        gemm_tn<false><<<grid, 256>>>(valid, D, gru_wih_b, D, gru_bih_b,
                                      GI + 768, GI_W, B * T, 768, D);
    }

    // 3) GRU recurrence (persistent, software grid sync)
    {
        int smem = (12 * 65 + 64 * 65) * (int)sizeof(float4);   // 79040 B
        cudaFuncSetAttribute(gru_kernel, cudaFuncAttributeMaxDynamicSharedMemorySize, smem);
        gru_kernel<<<GRU_BLOCKS, 256, smem>>>(GI, gru_whh_f, gru_whh_b,
                                              gru_bhh_f, gru_bhh_b, feats);
    }

    // 4) semantic net
    gemm_tn<true><<<dim3(4096 / 64, 1), 256>>>(batch_attrs, A_, fc1_w, A_, fc1_b,
                                               attr1, 4096, C, 4096, A_);
    gemm_tn<true><<<dim3(512 / 64, 1), 256>>>(attr1, 4096, fc2_w, 4096, fc2_b,
                                              attr2, 512, C, 512, 4096);

    // 5) relation head (fused diff^2 + fc3 + relu + fc4)
    relation_kernel<<<dim3(C, B), 256>>>(feats, attr2, fc3_w, fc3_b, fc4_w, fc4_b, logits);

    // 6) softmax over dim0 per segment, mean over segments
    softmax_colreduce<<<T, 256>>>(logits, cmax, csum);
    softmax_out<<<(B * C + 255) / 256, 256>>>(logits, cmax, csum, out);
}

// round 2
// speedup vs baseline: 1.1540x; 1.1540x over previous
#include <cuda_runtime.h>
#include <math.h>
#include <stdint.h>

// ---------------------------------------------------------------------------
// Problem constants
// ---------------------------------------------------------------------------
#define B    64
#define T    32      // == SEG
#define D    4096
#define C    50
#define A_   300
#define H    256     // GRU hidden per direction
#define GI_W 1536    // 768 fwd + 768 bwd

// ---------------------------------------------------------------------------
// Scratch (static device globals; no allocation allowed)
// ---------------------------------------------------------------------------
__device__ float g_valid[B * T * D];        // 33.5 MB
__device__ float g_GI[B * T * GI_W];        // 12.6 MB   [b][s][1536]
__device__ float g_feats[B * T * 512];      // 4.2 MB    [b][s][512]
__device__ float g_attr1[C * 4096];
__device__ float g_attr2[C * 512];
__device__ float g_logits[B * C * T];       // [row=b*C+c][s]
__device__ float g_cmax[T];
__device__ float g_csum[T];
__device__ float g_hbuf[2 * 2 * B * H];     // [phase][dir][b][i]
__device__ float g_wih_pack[GI_W * D];      // fwd 768 rows then bwd 768 rows
__device__ float g_bih_pack[GI_W];
__device__ int          g_bar_count;
__device__ unsigned int g_bar_gen;

// ---------------------------------------------------------------------------
// 0) Pack both GRU input weights/biases into one [1536,4096] matrix
// ---------------------------------------------------------------------------
__global__ __launch_bounds__(256) void pack_wih(
    const float* __restrict__ wf, const float* __restrict__ wb,
    const float* __restrict__ bf, const float* __restrict__ bb,
    float* __restrict__ wp, float* __restrict__ bp)
{
    int i = blockIdx.x * 256 + threadIdx.x;           // float4 index
    const int TOT4 = GI_W * D / 4;                    // 1,572,864
    if (i < TOT4) {
        int row = (i * 4) / D;
        float4 v;
        if (row < 768) v = ((const float4*)wf)[i];
        else           v = ((const float4*)wb)[i - 768 * D / 4];
        ((float4*)wp)[i] = v;
    }
    if (i < GI_W) bp[i] = (i < 768) ? bf[i] : bb[i - 768];
}

// ---------------------------------------------------------------------------
// 1) Segment selection
// ---------------------------------------------------------------------------
__global__ __launch_bounds__(256) void select_kernel(
    const float* __restrict__ bf,    // [B,T,D]
    const float* __restrict__ att,   // [B,T]
    float* __restrict__ valid)       // [B,T,D]
{
    int b = blockIdx.x;
    __shared__ float attS[T];
    __shared__ int   order[T];
    __shared__ int   cnt;
    int tid = threadIdx.x;

    if (tid < T) attS[tid] = att[b * T + tid];
    __syncthreads();
    if (tid == 0) {
        float s = 0.f;
        for (int t = 0; t < T; t++) s += attS[t];
        float thr = s / (float)T;
        int idx = 0;
        for (int t = 0; t < T; t++) if (attS[t] >= thr) order[idx++] = t;
        cnt = idx;
        for (int t = 0; t < T; t++) if (attS[t] <  thr) order[idx++] = t;
    }
    __syncthreads();

    for (int s = 0; s < T; s++) {
        const float4* src = (const float4*)(bf + ((size_t)b * T + order[s]) * D);
        float4*       dst = (float4*)(valid + ((size_t)b * T + s) * D);
        bool keep = (s < cnt);
        for (int t = tid; t < D / 4; t += 256)
            dst[t] = keep ? src[t] : make_float4(0.f, 0.f, 0.f, 0.f);
    }
}

// ---------------------------------------------------------------------------
// 2a) High-throughput fp32 GEMM: C[M,N] = A[M,K] * W[N,K]^T + bias
//     128x128 block tile, BK=16, 256 threads, 8x8/thread, LDS.128 everywhere.
//     Requires M%128==0, N%128==0, K%16==0.
// ---------------------------------------------------------------------------
__global__ __launch_bounds__(256) void gemm128(
    const float* __restrict__ A, int lda,
    const float* __restrict__ W, int ldw,
    const float* __restrict__ bias,
    float* __restrict__ Cg, int ldc, int K)
{
    __shared__ float As[16][132];
    __shared__ float Bs[16][132];
    int tid  = threadIdx.x;
    int row0 = blockIdx.y * 128;
    int col0 = blockIdx.x * 128;
    int ty = tid >> 4;            // 0..15
    int tx = tid & 15;            // 0..15
    int lr = tid >> 2;            // 0..63
    int lk = (tid & 3) * 4;       // 0,4,8,12

    float acc[8][8];
#pragma unroll
    for (int i = 0; i < 8; i++)
#pragma unroll
        for (int j = 0; j < 8; j++) acc[i][j] = 0.f;

    for (int k0 = 0; k0 < K; k0 += 16) {
#pragma unroll
        for (int half = 0; half < 2; half++) {
            int m = lr + half * 64;
            float4 av = *(const float4*)(A + (size_t)(row0 + m) * lda + k0 + lk);
            As[lk + 0][m] = av.x; As[lk + 1][m] = av.y;
            As[lk + 2][m] = av.z; As[lk + 3][m] = av.w;
            float4 wv = *(const float4*)(W + (size_t)(col0 + m) * ldw + k0 + lk);
            Bs[lk + 0][m] = wv.x; Bs[lk + 1][m] = wv.y;
            Bs[lk + 2][m] = wv.z; Bs[lk + 3][m] = wv.w;
        }
        __syncthreads();
#pragma unroll
        for (int kk = 0; kk < 16; kk++) {
            float4 a0 = *(const float4*)&As[kk][ty * 8];
            float4 a1 = *(const float4*)&As[kk][ty * 8 + 4];
            float4 b0 = *(const float4*)&Bs[kk][tx * 8];
            float4 b1 = *(const float4*)&Bs[kk][tx * 8 + 4];
            float a[8] = {a0.x, a0.y, a0.z, a0.w, a1.x, a1.y, a1.z, a1.w};
            float w[8] = {b0.x, b0.y, b0.z, b0.w, b1.x, b1.y, b1.z, b1.w};
#pragma unroll
            for (int i = 0; i < 8; i++)
#pragma unroll
                for (int j = 0; j < 8; j++)
                    acc[i][j] = fmaf(a[i], w[j], acc[i][j]);
        }
        __syncthreads();
    }

    float4 bv0 = *(const float4*)(bias + col0 + tx * 8);
    float4 bv1 = *(const float4*)(bias + col0 + tx * 8 + 4);
#pragma unroll
    for (int i = 0; i < 8; i++) {
        int r = row0 + ty * 8 + i;
        float4 o0 = make_float4(acc[i][0] + bv0.x, acc[i][1] + bv0.y,
                                acc[i][2] + bv0.z, acc[i][3] + bv0.w);
        float4 o1 = make_float4(acc[i][4] + bv1.x, acc[i][5] + bv1.y,
                                acc[i][6] + bv1.z, acc[i][7] + bv1.w);
        *(float4*)(Cg + (size_t)r * ldc + col0 + tx * 8)     = o0;
        *(float4*)(Cg + (size_t)r * ldc + col0 + tx * 8 + 4) = o1;
    }
}

// ---------------------------------------------------------------------------
// 2b) Generic small GEMM (used for fc1/fc2 where M=50)
// ---------------------------------------------------------------------------
template <bool RELU>
__global__ __launch_bounds__(256) void gemm_tn(
    const float* __restrict__ Ag, int lda,
    const float* __restrict__ Wg, int ldw,
    const float* __restrict__ bias,
    float* __restrict__ Cg, int ldc,
    int M, int N, int K)
{
    __shared__ float As[16][65];
    __shared__ float Ws[16][65];
    int tid  = threadIdx.x;
    int row0 = blockIdx.y * 64;
    int col0 = blockIdx.x * 64;
    int lm = tid >> 2;
    int lk = (tid & 3) * 4;
    int ty = tid >> 4;
    int tx = tid & 15;
    float acc[4][4];
#pragma unroll
    for (int i = 0; i < 4; i++)
#pragma unroll
        for (int j = 0; j < 4; j++) acc[i][j] = 0.f;

    for (int k0 = 0; k0 < K; k0 += 16) {
        int r = row0 + lm;
        int c = col0 + lm;
#pragma unroll
        for (int i = 0; i < 4; i++) {
            int k = k0 + lk + i;
            As[lk + i][lm] = (r < M && k < K) ? Ag[(size_t)r * lda + k] : 0.f;
            Ws[lk + i][lm] = (c < N && k < K) ? Wg[(size_t)c * ldw + k] : 0.f;
        }
        __syncthreads();
#pragma unroll
        for (int kk = 0; kk < 16; kk++) {
            float a[4], w[4];
#pragma unroll
            for (int i = 0; i < 4; i++) a[i] = As[kk][ty + 16 * i];
#pragma unroll
            for (int j = 0; j < 4; j++) w[j] = Ws[kk][tx + 16 * j];
#pragma unroll
            for (int i = 0; i < 4; i++)
#pragma unroll
                for (int j = 0; j < 4; j++)
                    acc[i][j] = fmaf(a[i], w[j], acc[i][j]);
        }
        __syncthreads();
    }

#pragma unroll
    for (int i = 0; i < 4; i++) {
        int r = row0 + ty + 16 * i;
        if (r >= M) continue;
#pragma unroll
        for (int j = 0; j < 4; j++) {
            int c = col0 + tx + 16 * j;
            if (c >= N) continue;
            float v = acc[i][j] + bias[c];
            if (RELU) v = fmaxf(v, 0.f);
            Cg[(size_t)r * ldc + c] = v;
        }
    }
}

// ---------------------------------------------------------------------------
// 3) GRU recurrence — persistent kernel, software grid barrier, 128 blocks.
// ---------------------------------------------------------------------------
#define GRU_BLOCKS 128

__device__ __forceinline__ void grid_barrier()
{
    __syncthreads();
    __threadfence();
    if (threadIdx.x == 0) {
        unsigned int g = *(volatile unsigned int*)&g_bar_gen;
        int t = atomicAdd(&g_bar_count, 1);
        if (t == GRU_BLOCKS - 1) {
            g_bar_count = 0;
            __threadfence();
            atomicExch(&g_bar_gen, g + 1);
        } else {
            while (*(volatile unsigned int*)&g_bar_gen == g) { __nanosleep(32); }
        }
    }
    __syncthreads();
    __threadfence();
}

__global__ __launch_bounds__(256) void gru_kernel(
    const float* __restrict__ GI,      // [b][s][1536]
    const float* __restrict__ whh_f,   // [768,256]
    const float* __restrict__ whh_b,
    const float* __restrict__ bhh_f,   // [768]
    const float* __restrict__ bhh_b,
    float* __restrict__ feats)         // [b][s][512]
{
    extern __shared__ float4 sm4[];
    float4* sW4 = sm4;                 // [12][65]
    float4* hS4 = sm4 + 12 * 65;       // [64][65]

    int d  = blockIdx.x >> 6;
    int hc = blockIdx.x & 63;
    int tid = threadIdx.x;
    int b = tid >> 2;
    int u = tid & 3;
    int i = hc * 4 + u;

    const float* whh = d ? whh_b : whh_f;
    const float* bhh = d ? bhh_b : bhh_f;

    for (int t = tid; t < 12 * 64; t += 256) {
        int rr = t >> 6;
        int k4 = t & 63;
        int g  = rr >> 2, uu = rr & 3;
        int row = g * H + hc * 4 + uu;
        sW4[rr * 65 + k4] = ((const float4*)(whh + (size_t)row * H))[k4];
    }
    float br = bhh[i], bz = bhh[H + i], bn = bhh[2 * H + i];

    float h = 0.f;
    g_hbuf[d * (B * H) + b * H + i] = 0.f;
    grid_barrier();

    for (int t = 0; t < T; t++) {
        int p = t & 1;
        const float4* hp4 = (const float4*)(g_hbuf + p * (2 * B * H) + d * (B * H));
        for (int idx = tid; idx < B * (H / 4); idx += 256)
            hS4[(idx >> 6) * 65 + (idx & 63)] = hp4[idx];
        __syncthreads();

        const float4* hb = &hS4[b * 65];
        const float4* wr = &sW4[(0 + u) * 65];
        const float4* wz = &sW4[(4 + u) * 65];
        const float4* wn = &sW4[(8 + u) * 65];
        float ar = 0.f, az = 0.f, an = 0.f;
#pragma unroll 16
        for (int k4 = 0; k4 < 64; k4++) {
            float4 hv = hb[k4];
            float4 a  = wr[k4];
            ar = fmaf(hv.x, a.x, fmaf(hv.y, a.y, fmaf(hv.z, a.z, fmaf(hv.w, a.w, ar))));
            float4 zz = wz[k4];
            az = fmaf(hv.x, zz.x, fmaf(hv.y, zz.y, fmaf(hv.z, zz.z, fmaf(hv.w, zz.w, az))));
            float4 nn = wn[k4];
            an = fmaf(hv.x, nn.x, fmaf(hv.y, nn.y, fmaf(hv.z, nn.z, fmaf(hv.w, nn.w, an))));
        }

        int s = d ? (T - 1 - t) : t;
        const float* gi = GI + ((size_t)b * T + s) * GI_W + d * 768;
        float ir  = gi[i];
        float iz  = gi[H + i];
        float in_ = gi[2 * H + i];

        float r = 1.f / (1.f + expf(-(ir + ar + br)));
        float z = 1.f / (1.f + expf(-(iz + az + bz)));
        float n = tanhf(in_ + r * (an + bn));
        h = (1.f - z) * n + z * h;

        feats[((size_t)b * T + s) * 512 + d * H + i] = h;
        g_hbuf[(p ^ 1) * (2 * B * H) + d * (B * H) + b * H + i] = h;

        grid_barrier();
    }
}

// ---------------------------------------------------------------------------
// 4) Fused relation head, vectorized: one block per (c,b).
//    dSt stored transposed [kk][s] so the a-operand is one broadcast LDS.128.
//    Inner step: 3 LDS.128 + 32 FMA.
// ---------------------------------------------------------------------------
__global__ __launch_bounds__(256) void relation_kernel(
    const float* __restrict__ feats,   // [B,T,512]
    const float* __restrict__ attr2,   // [C,512]
    const float* __restrict__ w3,      // [256,512]
    const float* __restrict__ b3,      // [256]
    const float* __restrict__ w4,      // [256]
    const float* __restrict__ b4,      // [1]
    float* __restrict__ logits)        // [B*C, T]
{
    int c = blockIdx.x;   // 0..49
    int b = blockIdx.y;   // 0..63
    int tid = threadIdx.x;
    __shared__ float aS[512];
    __shared__ float dSt[16][36];      // [kk][s]
    __shared__ float wS[16][264];      // [kk][j]
    __shared__ float part[32][33];

    for (int t = tid; t < 512; t += 256) aS[t] = attr2[(size_t)c * 512 + t];

    int tj = tid & 31;    // owns j = tj*8 .. tj*8+7
    int ts = tid >> 5;    // owns s = ts*4 .. ts*4+3
    float acc[4][8];
#pragma unroll
    for (int i = 0; i < 4; i++)
#pragma unroll
        for (int m = 0; m < 8; m++) acc[i][m] = 0.f;
    __syncthreads();

    for (int k0 = 0; k0 < 512; k0 += 16) {
        // W3 tile: thread tid owns row j=tid, 16 k values
        const float4* wrow = (const float4*)(w3 + (size_t)tid * 512 + k0);
        float4 v0 = wrow[0], v1 = wrow[1], v2 = wrow[2], v3 = wrow[3];
        wS[0][tid]  = v0.x; wS[1][tid]  = v0.y; wS[2][tid]  = v0.z; wS[3][tid]  = v0.w;
        wS[4][tid]  = v1.x; wS[5][tid]  = v1.y; wS[6][tid]  = v1.z; wS[7][tid]  = v1.w;
        wS[8][tid]  = v2.x; wS[9][tid]  = v2.y; wS[10][tid] = v2.z; wS[11][tid] = v2.w;
        wS[12][tid] = v3.x; wS[13][tid] = v3.y; wS[14][tid] = v3.z; wS[15][tid] = v3.w;
        // diff^2 tile (transposed)
        if (tid < 128) {
            int s  = tid >> 2;
            int kq = (tid & 3) * 4;
            float4 f = *(const float4*)(feats + ((size_t)b * T + s) * 512 + k0 + kq);
            float d0 = f.x - aS[k0 + kq + 0];
            float d1 = f.y - aS[k0 + kq + 1];
            float d2 = f.z - aS[k0 + kq + 2];
            float d3 = f.w - aS[k0 + kq + 3];
            dSt[kq + 0][s] = d0 * d0;
            dSt[kq + 1][s] = d1 * d1;
            dSt[kq + 2][s] = d2 * d2;
            dSt[kq + 3][s] = d3 * d3;
        }
        __syncthreads();
#pragma unroll
        for (int kk = 0; kk < 16; kk++) {
            float4 av = *(const float4*)&dSt[kk][ts * 4];
            float4 w0 = *(const float4*)&wS[kk][tj * 8];
            float4 w1 = *(const float4*)&wS[kk][tj * 8 + 4];
            float a[4] = {av.x, av.y, av.z, av.w};
            float w[8] = {w0.x, w0.y, w0.z, w0.w, w1.x, w1.y, w1.z, w1.w};
#pragma unroll
            for (int i = 0; i < 4; i++)
#pragma unroll
                for (int m = 0; m < 8; m++)
                    acc[i][m] = fmaf(a[i], w[m], acc[i][m]);
        }
        __syncthreads();
    }

    // relu + fc4 dot over this thread's 8 contiguous j columns
#pragma unroll
    for (int i = 0; i < 4; i++) {
        float p = 0.f;
#pragma unroll
        for (int m = 0; m < 8; m++) {
            int j = tj * 8 + m;
            float hh = fmaxf(acc[i][m] + b3[j], 0.f);
            p = fmaf(hh, w4[j], p);
        }
        part[ts * 4 + i][tj] = p;
    }
    __syncthreads();
    if (tid < 32) {
        float s = b4[0];
        for (int t2 = 0; t2 < 32; t2++) s += part[tid][t2];
        logits[((size_t)b * C + c) * T + tid] = s;
    }
}

// ---------------------------------------------------------------------------
// 5) Softmax over dim-0 per segment column, then mean over columns
// ---------------------------------------------------------------------------
__global__ __launch_bounds__(256) void softmax_colreduce(
    const float* __restrict__ logits, float* __restrict__ cmax, float* __restrict__ csum)
{
    int t = blockIdx.x;
    int tid = threadIdx.x;
    __shared__ float red[256];
    float m = -1e30f;
    for (int i = tid; i < B * C; i += 256) m = fmaxf(m, logits[(size_t)i * T + t]);
    red[tid] = m; __syncthreads();
    for (int s = 128; s > 0; s >>= 1) {
        if (tid < s) red[tid] = fmaxf(red[tid], red[tid + s]);
        __syncthreads();
    }
    float mx = red[0];
    __syncthreads();
    float sum = 0.f;
    for (int i = tid; i < B * C; i += 256) sum += expf(logits[(size_t)i * T + t] - mx);
    red[tid] = sum; __syncthreads();
    for (int s = 128; s > 0; s >>= 1) {
        if (tid < s) red[tid] += red[tid + s];
        __syncthreads();
    }
    if (tid == 0) { cmax[t] = mx; csum[t] = red[0]; }
}

__global__ __launch_bounds__(256) void softmax_out(
    const float* __restrict__ logits, const float* __restrict__ cmax,
    const float* __restrict__ csum, float* __restrict__ out)
{
    __shared__ float mS[T], sS[T];
    int tid = threadIdx.x;
    if (tid < T) { mS[tid] = cmax[tid]; sS[tid] = csum[tid]; }
    __syncthreads();
    int i = blockIdx.x * 256 + tid;
    if (i < B * C) {
        float a = 0.f;
        const float* row = logits + (size_t)i * T;
#pragma unroll
        for (int t = 0; t < T; t++) a += expf(row[t] - mS[t]) / sS[t];
        out[i] = a * (1.f / (float)T);
    }
}

// ---------------------------------------------------------------------------
// Launch
// ---------------------------------------------------------------------------
extern "C" void kernel_launch(void* const* d_in, const int* in_sizes, int n_in,
                              void* d_out, int out_size)
{
    const float* batch_features  = (const float*)d_in[0];
    const float* batch_att       = (const float*)d_in[1];
    const float* batch_attrs     = (const float*)d_in[2];
    const float* fc1_w = (const float*)d_in[3];
    const float* fc1_b = (const float*)d_in[4];
    const float* fc2_w = (const float*)d_in[5];
    const float* fc2_b = (const float*)d_in[6];
    const float* fc3_w = (const float*)d_in[7];
    const float* fc3_b = (const float*)d_in[8];
    const float* fc4_w = (const float*)d_in[9];
    const float* fc4_b = (const float*)d_in[10];
    const float* gru_wih_f = (const float*)d_in[11];
    const float* gru_whh_f = (const float*)d_in[12];
    const float* gru_bih_f = (const float*)d_in[13];
    const float* gru_bhh_f = (const float*)d_in[14];
    const float* gru_wih_b = (const float*)d_in[15];
    const float* gru_whh_b = (const float*)d_in[16];
    const float* gru_bih_b = (const float*)d_in[17];
    const float* gru_bhh_b = (const float*)d_in[18];
    float* out = (float*)d_out;

    float* valid;  cudaGetSymbolAddress((void**)&valid,  g_valid);
    float* GI;     cudaGetSymbolAddress((void**)&GI,     g_GI);
    float* feats;  cudaGetSymbolAddress((void**)&feats,  g_feats);
    float* attr1;  cudaGetSymbolAddress((void**)&attr1,  g_attr1);
    float* attr2;  cudaGetSymbolAddress((void**)&attr2,  g_attr2);
    float* logits; cudaGetSymbolAddress((void**)&logits, g_logits);
    float* cmax;   cudaGetSymbolAddress((void**)&cmax,   g_cmax);
    float* csum;   cudaGetSymbolAddress((void**)&csum,   g_csum);
    float* wpack;  cudaGetSymbolAddress((void**)&wpack,  g_wih_pack);
    float* bpack;  cudaGetSymbolAddress((void**)&bpack,  g_bih_pack);

    // 0) pack GRU input weights (fwd+bwd) into one matrix
    pack_wih<<<(GI_W * D / 4 + 255) / 256, 256>>>(gru_wih_f, gru_wih_b,
                                                  gru_bih_f, gru_bih_b, wpack, bpack);

    // 1) segment selection
    select_kernel<<<B, 256>>>(batch_features, batch_att, valid);

    // 2) fused GRU input projection: [2048,4096] x [1536,4096]^T
    {
        dim3 grid(GI_W / 128, (B * T) / 128);   // (12, 16)
        gemm128<<<grid, 256>>>(valid, D, wpack, D, bpack, GI, GI_W, D);
    }

    // 3) GRU recurrence (persistent, software grid sync)
    {
        int smem = (12 * 65 + 64 * 65) * (int)sizeof(float4);
        cudaFuncSetAttribute(gru_kernel, cudaFuncAttributeMaxDynamicSharedMemorySize, smem);
        gru_kernel<<<GRU_BLOCKS, 256, smem>>>(GI, gru_whh_f, gru_whh_b,
                                              gru_bhh_f, gru_bhh_b, feats);
    }

    // 4) semantic net
    gemm_tn<true><<<dim3(4096 / 64, 1), 256>>>(batch_attrs, A_, fc1_w, A_, fc1_b,
                                               attr1, 4096, C, 4096, A_);
    gemm_tn<true><<<dim3(512 / 64, 1), 256>>>(attr1, 4096, fc2_w, 4096, fc2_b,
                                              attr2, 512, C, 512, 4096);

    // 5) relation head (fused diff^2 + fc3 + relu + fc4)
    relation_kernel<<<dim3(C, B), 256>>>(feats, attr2, fc3_w, fc3_b, fc4_w, fc4_b, logits);

    // 6) softmax over dim0 per segment, mean over segments
    softmax_colreduce<<<T, 256>>>(logits, cmax, csum);
    softmax_out<<<(B * C + 255) / 256, 256>>>(logits, cmax, csum, out);
}

// round 3
// speedup vs baseline: 1.6495x; 1.4294x over previous
#include <cuda_runtime.h>
#include <math.h>
#include <stdint.h>

#define B    64
#define T    32
#define D    4096
#define C    50
#define A_   300
#define H    256
#define GI_W 1536

// ---------------------------------------------------------------------------
// Scratch
// ---------------------------------------------------------------------------
__device__ float g_valid[B * T * D];
__device__ float g_GI[B * T * GI_W];
__device__ float g_feats[B * T * 512];
__device__ float g_attr1[C * 4096];
__device__ float g_attr2[C * 512];
__device__ float g_logits[B * C * T];
__device__ float g_cmax[T];
__device__ float g_csum[T];
__device__ float g_hbuf[2 * 2 * B * H];
__device__ float g_wih_pack[GI_W * D];
__device__ float g_bih_pack[GI_W];
__device__ int          g_bar_count;
__device__ unsigned int g_bar_gen;

// ---------------------------------------------------------------------------
// tf32 helpers
// ---------------------------------------------------------------------------
__device__ __forceinline__ void mma8(float* c, const uint32_t* a, const uint32_t* b)
{
    asm volatile(
        "mma.sync.aligned.m16n8k8.row.col.f32.tf32.tf32.f32 "
        "{%0,%1,%2,%3},{%4,%5,%6,%7},{%8,%9},{%0,%1,%2,%3};"
        : "+f"(c[0]), "+f"(c[1]), "+f"(c[2]), "+f"(c[3])
        : "r"(a[0]), "r"(a[1]), "r"(a[2]), "r"(a[3]), "r"(b[0]), "r"(b[1]));
}

__device__ __forceinline__ void split1(float v, float& h, float& l)
{
    uint32_t u;
    asm("cvt.rna.tf32.f32 %0, %1;" : "=r"(u) : "f"(v));
    h = __uint_as_float(u);
    l = v - h;
}
__device__ __forceinline__ void split4(float4 v, float4& h, float4& l)
{
    split1(v.x, h.x, l.x); split1(v.y, h.y, l.y);
    split1(v.z, h.z, l.z); split1(v.w, h.w, l.w);
}

// ---------------------------------------------------------------------------
// 0) Pack GRU input weights/biases
// ---------------------------------------------------------------------------
__global__ __launch_bounds__(256) void pack_wih(
    const float* __restrict__ wf, const float* __restrict__ wb,
    const float* __restrict__ bf, const float* __restrict__ bb,
    float* __restrict__ wp, float* __restrict__ bp)
{
    int i = blockIdx.x * 256 + threadIdx.x;
    const int TOT4 = GI_W * D / 4;
    if (i < TOT4) {
        int row = (i * 4) / D;
        float4 v;
        if (row < 768) v = ((const float4*)wf)[i];
        else           v = ((const float4*)wb)[i - 768 * D / 4];
        ((float4*)wp)[i] = v;
    }
    if (i < GI_W) bp[i] = (i < 768) ? bf[i] : bb[i - 768];
}

// ---------------------------------------------------------------------------
// 1) Segment selection
// ---------------------------------------------------------------------------
__global__ __launch_bounds__(256) void select_kernel(
    const float* __restrict__ bf, const float* __restrict__ att,
    float* __restrict__ valid)
{
    int b = blockIdx.x;
    __shared__ float attS[T];
    __shared__ int   order[T];
    __shared__ int   cnt;
    int tid = threadIdx.x;

    if (tid < T) attS[tid] = att[b * T + tid];
    __syncthreads();
    if (tid == 0) {
        float s = 0.f;
        for (int t = 0; t < T; t++) s += attS[t];
        float thr = s / (float)T;
        int idx = 0;
        for (int t = 0; t < T; t++) if (attS[t] >= thr) order[idx++] = t;
        cnt = idx;
        for (int t = 0; t < T; t++) if (attS[t] <  thr) order[idx++] = t;
    }
    __syncthreads();

    for (int s = 0; s < T; s++) {
        const float4* src = (const float4*)(bf + ((size_t)b * T + order[s]) * D);
        float4*       dst = (float4*)(valid + ((size_t)b * T + s) * D);
        bool keep = (s < cnt);
        for (int t = tid; t < D / 4; t += 256)
            dst[t] = keep ? src[t] : make_float4(0.f, 0.f, 0.f, 0.f);
    }
}

// ---------------------------------------------------------------------------
// 2) GI projection on tensor cores: C[2048,1536] = A[2048,4096]*W[1536,4096]^T
//    3xTF32 (hi*hi + lo*hi + hi*lo). Block tile 128x64, 256 thr, 8 warps.
//    Warp tile 32x32 (wm 0-3, wn 0-1; 2 m-tiles x 4 n-tiles of m16n8k8).
// ---------------------------------------------------------------------------
__global__ __launch_bounds__(256) void gemm_mma_gi(
    const float* __restrict__ A,
    const float* __restrict__ W,
    const float* __restrict__ bias,
    float* __restrict__ Cg)
{
    __shared__ float Ah[128][20], Al[128][20], Wh[64][20], Wl[64][20];
    int tid  = threadIdx.x;
    int lane = tid & 31, warp = tid >> 5;
    int wm = warp >> 1, wn = warp & 1;
    int g  = lane >> 2, tg = lane & 3;
    int row0 = blockIdx.y * 128, col0 = blockIdx.x * 64;

    float c[2][4][4];
#pragma unroll
    for (int mt = 0; mt < 2; mt++)
#pragma unroll
        for (int nt = 0; nt < 4; nt++)
#pragma unroll
            for (int r = 0; r < 4; r++) c[mt][nt][r] = 0.f;

    int lr = tid >> 1;
    int lk = (tid & 1) * 8;

    for (int k0 = 0; k0 < D; k0 += 16) {
        {
            const float* src = A + (size_t)(row0 + lr) * D + k0 + lk;
            float4 v0 = *(const float4*)src;
            float4 v1 = *(const float4*)(src + 4);
            float4 h, l;
            split4(v0, h, l);
            *(float4*)&Ah[lr][lk] = h; *(float4*)&Al[lr][lk] = l;
            split4(v1, h, l);
            *(float4*)&Ah[lr][lk + 4] = h; *(float4*)&Al[lr][lk + 4] = l;
        }
        if (tid < 128) {
            int wr = tid >> 1;
            const float* src = W + (size_t)(col0 + wr) * D + k0 + lk;
            float4 v0 = *(const float4*)src;
            float4 v1 = *(const float4*)(src + 4);
            float4 h, l;
            split4(v0, h, l);
            *(float4*)&Wh[wr][lk] = h; *(float4*)&Wl[wr][lk] = l;
            split4(v1, h, l);
            *(float4*)&Wh[wr][lk + 4] = h; *(float4*)&Wl[wr][lk + 4] = l;
        }
        __syncthreads();

#pragma unroll
        for (int ks = 0; ks < 2; ks++) {
            int kb = ks * 8;
            uint32_t ah[2][4], al[2][4];
#pragma unroll
            for (int mt = 0; mt < 2; mt++) {
                int m0 = wm * 32 + mt * 16;
                ah[mt][0] = __float_as_uint(Ah[m0 + g][kb + tg]);
                ah[mt][1] = __float_as_uint(Ah[m0 + g + 8][kb + tg]);
                ah[mt][2] = __float_as_uint(Ah[m0 + g][kb + tg + 4]);
                ah[mt][3] = __float_as_uint(Ah[m0 + g + 8][kb + tg + 4]);
                al[mt][0] = __float_as_uint(Al[m0 + g][kb + tg]);
                al[mt][1] = __float_as_uint(Al[m0 + g + 8][kb + tg]);
                al[mt][2] = __float_as_uint(Al[m0 + g][kb + tg + 4]);
                al[mt][3] = __float_as_uint(Al[m0 + g + 8][kb + tg + 4]);
            }
#pragma unroll
            for (int nt = 0; nt < 4; nt++) {
                int n0 = wn * 32 + nt * 8;
                uint32_t bh[2], bl[2];
                bh[0] = __float_as_uint(Wh[n0 + g][kb + tg]);
                bh[1] = __float_as_uint(Wh[n0 + g][kb + tg + 4]);
                bl[0] = __float_as_uint(Wl[n0 + g][kb + tg]);
                bl[1] = __float_as_uint(Wl[n0 + g][kb + tg + 4]);
#pragma unroll
                for (int mt = 0; mt < 2; mt++) {
                    mma8(c[mt][nt], ah[mt], bh);
                    mma8(c[mt][nt], al[mt], bh);
                    mma8(c[mt][nt], ah[mt], bl);
                }
            }
        }
        __syncthreads();
    }

#pragma unroll
    for (int mt = 0; mt < 2; mt++) {
        int row = row0 + wm * 32 + mt * 16 + g;
#pragma unroll
        for (int nt = 0; nt < 4; nt++) {
            int col = col0 + wn * 32 + nt * 8 + 2 * tg;
            float b0 = bias[col], b1 = bias[col + 1];
            float2 o0 = make_float2(c[mt][nt][0] + b0, c[mt][nt][1] + b1);
            float2 o1 = make_float2(c[mt][nt][2] + b0, c[mt][nt][3] + b1);
            *(float2*)(Cg + (size_t)row * GI_W + col)       = o0;
            *(float2*)(Cg + (size_t)(row + 8) * GI_W + col) = o1;
        }
    }
}

// ---------------------------------------------------------------------------
// 2b) Small-M fallback GEMM (fc1/fc2)
// ---------------------------------------------------------------------------
template <bool RELU>
__global__ __launch_bounds__(256) void gemm_tn(
    const float* __restrict__ Ag, int lda,
    const float* __restrict__ Wg, int ldw,
    const float* __restrict__ bias,
    float* __restrict__ Cg, int ldc,
    int M, int N, int K)
{
    __shared__ float As[16][65];
    __shared__ float Ws[16][65];
    int tid  = threadIdx.x;
    int row0 = blockIdx.y * 64;
    int col0 = blockIdx.x * 64;
    int lm = tid >> 2;
    int lk = (tid & 3) * 4;
    int ty = tid >> 4;
    int tx = tid & 15;
    float acc[4][4];
#pragma unroll
    for (int i = 0; i < 4; i++)
#pragma unroll
        for (int j = 0; j < 4; j++) acc[i][j] = 0.f;

    for (int k0 = 0; k0 < K; k0 += 16) {
        int r = row0 + lm;
        int cc = col0 + lm;
#pragma unroll
        for (int i = 0; i < 4; i++) {
            int k = k0 + lk + i;
            As[lk + i][lm] = (r < M && k < K) ? Ag[(size_t)r * lda + k] : 0.f;
            Ws[lk + i][lm] = (cc < N && k < K) ? Wg[(size_t)cc * ldw + k] : 0.f;
        }
        __syncthreads();
#pragma unroll
        for (int kk = 0; kk < 16; kk++) {
            float a[4], w[4];
#pragma unroll
            for (int i = 0; i < 4; i++) a[i] = As[kk][ty + 16 * i];
#pragma unroll
            for (int j = 0; j < 4; j++) w[j] = Ws[kk][tx + 16 * j];
#pragma unroll
            for (int i = 0; i < 4; i++)
#pragma unroll
                for (int j = 0; j < 4; j++)
                    acc[i][j] = fmaf(a[i], w[j], acc[i][j]);
        }
        __syncthreads();
    }

#pragma unroll
    for (int i = 0; i < 4; i++) {
        int r = row0 + ty + 16 * i;
        if (r >= M) continue;
#pragma unroll
        for (int j = 0; j < 4; j++) {
            int cc = col0 + tx + 16 * j;
            if (cc >= N) continue;
            float v = acc[i][j] + bias[cc];
            if (RELU) v = fmaxf(v, 0.f);
            Cg[(size_t)r * ldc + cc] = v;
        }
    }
}

// ---------------------------------------------------------------------------
// 3) GRU recurrence (unchanged)
// ---------------------------------------------------------------------------
#define GRU_BLOCKS 128

__device__ __forceinline__ void grid_barrier()
{
    __syncthreads();
    __threadfence();
    if (threadIdx.x == 0) {
        unsigned int g = *(volatile unsigned int*)&g_bar_gen;
        int t = atomicAdd(&g_bar_count, 1);
        if (t == GRU_BLOCKS - 1) {
            g_bar_count = 0;
            __threadfence();
            atomicExch(&g_bar_gen, g + 1);
        } else {
            while (*(volatile unsigned int*)&g_bar_gen == g) { __nanosleep(32); }
        }
    }
    __syncthreads();
    __threadfence();
}

__global__ __launch_bounds__(256) void gru_kernel(
    const float* __restrict__ GI,
    const float* __restrict__ whh_f, const float* __restrict__ whh_b,
    const float* __restrict__ bhh_f, const float* __restrict__ bhh_b,
    float* __restrict__ feats)
{
    extern __shared__ float4 sm4[];
    float4* sW4 = sm4;
    float4* hS4 = sm4 + 12 * 65;

    int d  = blockIdx.x >> 6;
    int hc = blockIdx.x & 63;
    int tid = threadIdx.x;
    int b = tid >> 2;
    int u = tid & 3;
    int i = hc * 4 + u;

    const float* whh = d ? whh_b : whh_f;
    const float* bhh = d ? bhh_b : bhh_f;

    for (int t = tid; t < 12 * 64; t += 256) {
        int rr = t >> 6;
        int k4 = t & 63;
        int g  = rr >> 2, uu = rr & 3;
        int row = g * H + hc * 4 + uu;
        sW4[rr * 65 + k4] = ((const float4*)(whh + (size_t)row * H))[k4];
    }
    float br = bhh[i], bz = bhh[H + i], bn = bhh[2 * H + i];

    float h = 0.f;
    g_hbuf[d * (B * H) + b * H + i] = 0.f;
    grid_barrier();

    for (int t = 0; t < T; t++) {
        int p = t & 1;
        const float4* hp4 = (const float4*)(g_hbuf + p * (2 * B * H) + d * (B * H));
        for (int idx = tid; idx < B * (H / 4); idx += 256)
            hS4[(idx >> 6) * 65 + (idx & 63)] = hp4[idx];
        __syncthreads();

        const float4* hb = &hS4[b * 65];
        const float4* wr = &sW4[(0 + u) * 65];
        const float4* wz = &sW4[(4 + u) * 65];
        const float4* wn = &sW4[(8 + u) * 65];
        float ar = 0.f, az = 0.f, an = 0.f;
#pragma unroll 16
        for (int k4 = 0; k4 < 64; k4++) {
            float4 hv = hb[k4];
            float4 a  = wr[k4];
            ar = fmaf(hv.x, a.x, fmaf(hv.y, a.y, fmaf(hv.z, a.z, fmaf(hv.w, a.w, ar))));
            float4 zz = wz[k4];
            az = fmaf(hv.x, zz.x, fmaf(hv.y, zz.y, fmaf(hv.z, zz.z, fmaf(hv.w, zz.w, az))));
            float4 nn = wn[k4];
            an = fmaf(hv.x, nn.x, fmaf(hv.y, nn.y, fmaf(hv.z, nn.z, fmaf(hv.w, nn.w, an))));
        }

        int s = d ? (T - 1 - t) : t;
        const float* gi = GI + ((size_t)b * T + s) * GI_W + d * 768;
        float ir  = gi[i];
        float iz  = gi[H + i];
        float in_ = gi[2 * H + i];

        float r = 1.f / (1.f + expf(-(ir + ar + br)));
        float z = 1.f / (1.f + expf(-(iz + az + bz)));
        float n = tanhf(in_ + r * (an + bn));
        h = (1.f - z) * n + z * h;

        feats[((size_t)b * T + s) * 512 + d * H + i] = h;
        g_hbuf[(p ^ 1) * (2 * B * H) + d * (B * H) + b * H + i] = h;

        grid_barrier();
    }
}

// ---------------------------------------------------------------------------
// 4) Relation head on tensor cores. One block per (2 classes, batch b).
//    M=64 (2c x 32s), N=256, K=512, 3xTF32, fused relu+fc4+reduce.
//    8 warps: wm=warp>>2 (0-1), wn=warp&3 (0-3). Warp tile 32x64.
// ---------------------------------------------------------------------------
#define REL_SMEM_FLOATS (64*20*2 + 256*20*2 + 2*512 + 64*5)

__global__ __launch_bounds__(256) void relation_mma(
    const float* __restrict__ feats,
    const float* __restrict__ attr2,
    const float* __restrict__ w3,
    const float* __restrict__ b3,
    const float* __restrict__ w4,
    const float* __restrict__ b4,
    float* __restrict__ logits)
{
    extern __shared__ float smemR[];
    float (*Dh)[20] = (float(*)[20])(smemR);
    float (*Dl)[20] = (float(*)[20])(smemR + 64 * 20);
    float (*Wh)[20] = (float(*)[20])(smemR + 64 * 20 * 2);
    float (*Wl)[20] = (float(*)[20])(smemR + 64 * 20 * 2 + 256 * 20);
    float* aS       = smemR + 64 * 20 * 2 + 256 * 20 * 2;          // [2][512]
    float (*part)[5]= (float(*)[5])(aS + 2 * 512);                 // [64][5]

    int c0 = blockIdx.x * 2;
    int b  = blockIdx.y;
    int tid  = threadIdx.x;
    int lane = tid & 31, warp = tid >> 5;
    int wm = warp >> 2, wn = warp & 3;
    int g  = lane >> 2, tg = lane & 3;

    for (int t = tid; t < 1024; t += 256)
        aS[t] = attr2[(size_t)(c0 + (t >> 9)) * 512 + (t & 511)];
    __syncthreads();

    float c[2][8][4];
#pragma unroll
    for (int mt = 0; mt < 2; mt++)
#pragma unroll
        for (int nt = 0; nt < 8; nt++)
#pragma unroll
            for (int r = 0; r < 4; r++) c[mt][nt][r] = 0.f;

    int dm = tid >> 2;                 // 0..63
    int dk = (tid & 3) * 4;
    int ds = dm & 31, dc = dm >> 5;
    const float* frow = feats + ((size_t)b * T + ds) * 512;

    for (int k0 = 0; k0 < 512; k0 += 16) {
        {
            float4 f = *(const float4*)(frow + k0 + dk);
            float4 a = *(const float4*)(aS + dc * 512 + k0 + dk);
            float4 dd;
            dd.x = (f.x - a.x) * (f.x - a.x);
            dd.y = (f.y - a.y) * (f.y - a.y);
            dd.z = (f.z - a.z) * (f.z - a.z);
            dd.w = (f.w - a.w) * (f.w - a.w);
            float4 h, l;
            split4(dd, h, l);
            *(float4*)&Dh[dm][dk] = h;
            *(float4*)&Dl[dm][dk] = l;
        }
        {
            const float* wr = w3 + (size_t)tid * 512 + k0;
            float4 h, l;
#pragma unroll
            for (int q = 0; q < 4; q++) {
                float4 v = *(const float4*)(wr + q * 4);
                split4(v, h, l);
                *(float4*)&Wh[tid][q * 4] = h;
                *(float4*)&Wl[tid][q * 4] = l;
            }
        }
        __syncthreads();

#pragma unroll
        for (int ks = 0; ks < 2; ks++) {
            int kb = ks * 8;
            uint32_t ah[2][4], al[2][4];
#pragma unroll
            for (int mt = 0; mt < 2; mt++) {
                int m0 = wm * 32 + mt * 16;
                ah[mt][0] = __float_as_uint(Dh[m0 + g][kb + tg]);
                ah[mt][1] = __float_as_uint(Dh[m0 + g + 8][kb + tg]);
                ah[mt][2] = __float_as_uint(Dh[m0 + g][kb + tg + 4]);
                ah[mt][3] = __float_as_uint(Dh[m0 + g + 8][kb + tg + 4]);
                al[mt][0] = __float_as_uint(Dl[m0 + g][kb + tg]);
                al[mt][1] = __float_as_uint(Dl[m0 + g + 8][kb + tg]);
                al[mt][2] = __float_as_uint(Dl[m0 + g][kb + tg + 4]);
                al[mt][3] = __float_as_uint(Dl[m0 + g + 8][kb + tg + 4]);
            }
#pragma unroll
            for (int nt = 0; nt < 8; nt++) {
                int n0 = wn * 64 + nt * 8;
                uint32_t bh[2], bl[2];
                bh[0] = __float_as_uint(Wh[n0 + g][kb + tg]);
                bh[1] = __float_as_uint(Wh[n0 + g][kb + tg + 4]);
                bl[0] = __float_as_uint(Wl[n0 + g][kb + tg]);
                bl[1] = __float_as_uint(Wl[n0 + g][kb + tg + 4]);
#pragma unroll
                for (int mt = 0; mt < 2; mt++) {
                    mma8(c[mt][nt], ah[mt], bh);
                    mma8(c[mt][nt], al[mt], bh);
                    mma8(c[mt][nt], ah[mt], bl);
                }
            }
        }
        __syncthreads();
    }

    // relu + fc4 dot, reduce over the warp's 64 n-columns
    float rs[2][2] = {{0.f, 0.f}, {0.f, 0.f}};
#pragma unroll
    for (int nt = 0; nt < 8; nt++) {
        int col = wn * 64 + nt * 8 + 2 * tg;
        float w40 = w4[col], w41 = w4[col + 1];
        float b30 = b3[col], b31 = b3[col + 1];
#pragma unroll
        for (int mt = 0; mt < 2; mt++) {
            rs[mt][0] += fmaxf(c[mt][nt][0] + b30, 0.f) * w40
                       + fmaxf(c[mt][nt][1] + b31, 0.f) * w41;
            rs[mt][1] += fmaxf(c[mt][nt][2] + b30, 0.f) * w40
                       + fmaxf(c[mt][nt][3] + b31, 0.f) * w41;
        }
    }
#pragma unroll
    for (int mt = 0; mt < 2; mt++)
#pragma unroll
        for (int hf = 0; hf < 2; hf++) {
            float v = rs[mt][hf];
            v += __shfl_xor_sync(0xffffffffu, v, 1);
            v += __shfl_xor_sync(0xffffffffu, v, 2);
            if (tg == 0)
                part[wm * 32 + mt * 16 + g + hf * 8][wn] = v;
        }
    __syncthreads();
    if (tid < 64) {
        float s = b4[0] + part[tid][0] + part[tid][1] + part[tid][2] + part[tid][3];
        int cc = c0 + (tid >> 5), ss = tid & 31;
        logits[((size_t)b * C + cc) * T + ss] = s;
    }
}

// ---------------------------------------------------------------------------
// 5) Softmax over dim-0 per column, mean over columns
// ---------------------------------------------------------------------------
__global__ __launch_bounds__(256) void softmax_colreduce(
    const float* __restrict__ logits, float* __restrict__ cmax, float* __restrict__ csum)
{
    int t = blockIdx.x;
    int tid = threadIdx.x;
    __shared__ float red[256];
    float m = -1e30f;
    for (int i = tid; i < B * C; i += 256) m = fmaxf(m, logits[(size_t)i * T + t]);
    red[tid] = m; __syncthreads();
    for (int s = 128; s > 0; s >>= 1) {
        if (tid < s) red[tid] = fmaxf(red[tid], red[tid + s]);
        __syncthreads();
    }
    float mx = red[0];
    __syncthreads();
    float sum = 0.f;
    for (int i = tid; i < B * C; i += 256) sum += expf(logits[(size_t)i * T + t] - mx);
    red[tid] = sum; __syncthreads();
    for (int s = 128; s > 0; s >>= 1) {
        if (tid < s) red[tid] += red[tid + s];
        __syncthreads();
    }
    if (tid == 0) { cmax[t] = mx; csum[t] = red[0]; }
}

__global__ __launch_bounds__(256) void softmax_out(
    const float* __restrict__ logits, const float* __restrict__ cmax,
    const float* __restrict__ csum, float* __restrict__ out)
{
    __shared__ float mS[T], sS[T];
    int tid = threadIdx.x;
    if (tid < T) { mS[tid] = cmax[tid]; sS[tid] = csum[tid]; }
    __syncthreads();
    int i = blockIdx.x * 256 + tid;
    if (i < B * C) {
        float a = 0.f;
        const float* row = logits + (size_t)i * T;
#pragma unroll
        for (int t = 0; t < T; t++) a += expf(row[t] - mS[t]) / sS[t];
        out[i] = a * (1.f / (float)T);
    }
}

// ---------------------------------------------------------------------------
// Launch
// ---------------------------------------------------------------------------
extern "C" void kernel_launch(void* const* d_in, const int* in_sizes, int n_in,
                              void* d_out, int out_size)
{
    const float* batch_features  = (const float*)d_in[0];
    const float* batch_att       = (const float*)d_in[1];
    const float* batch_attrs     = (const float*)d_in[2];
    const float* fc1_w = (const float*)d_in[3];
    const float* fc1_b = (const float*)d_in[4];
    const float* fc2_w = (const float*)d_in[5];
    const float* fc2_b = (const float*)d_in[6];
    const float* fc3_w = (const float*)d_in[7];
    const float* fc3_b = (const float*)d_in[8];
    const float* fc4_w = (const float*)d_in[9];
    const float* fc4_b = (const float*)d_in[10];
    const float* gru_wih_f = (const float*)d_in[11];
    const float* gru_whh_f = (const float*)d_in[12];
    const float* gru_bih_f = (const float*)d_in[13];
    const float* gru_bhh_f = (const float*)d_in[14];
    const float* gru_wih_b = (const float*)d_in[15];
    const float* gru_whh_b = (const float*)d_in[16];
    const float* gru_bih_b = (const float*)d_in[17];
    const float* gru_bhh_b = (const float*)d_in[18];
    float* out = (float*)d_out;

    float* valid;  cudaGetSymbolAddress((void**)&valid,  g_valid);
    float* GI;     cudaGetSymbolAddress((void**)&GI,     g_GI);
    float* feats;  cudaGetSymbolAddress((void**)&feats,  g_feats);
    float* attr1;  cudaGetSymbolAddress((void**)&attr1,  g_attr1);
    float* attr2;  cudaGetSymbolAddress((void**)&attr2,  g_attr2);
    float* logits; cudaGetSymbolAddress((void**)&logits, g_logits);
    float* cmax;   cudaGetSymbolAddress((void**)&cmax,   g_cmax);
    float* csum;   cudaGetSymbolAddress((void**)&csum,   g_csum);
    float* wpack;  cudaGetSymbolAddress((void**)&wpack,  g_wih_pack);
    float* bpack;  cudaGetSymbolAddress((void**)&bpack,  g_bih_pack);

    pack_wih<<<(GI_W * D / 4 + 255) / 256, 256>>>(gru_wih_f, gru_wih_b,
                                                  gru_bih_f, gru_bih_b, wpack, bpack);
    select_kernel<<<B, 256>>>(batch_features, batch_att, valid);

    // GI projection (tensor cores, 3xTF32)
    {
        dim3 grid(GI_W / 64, (B * T) / 128);   // (24, 16)
        gemm_mma_gi<<<grid, 256>>>(valid, wpack, bpack, GI);
    }

    // GRU recurrence
    {
        int smem = (12 * 65 + 64 * 65) * (int)sizeof(float4);
        cudaFuncSetAttribute(gru_kernel, cudaFuncAttributeMaxDynamicSharedMemorySize, smem);
        gru_kernel<<<GRU_BLOCKS, 256, smem>>>(GI, gru_whh_f, gru_whh_b,
                                              gru_bhh_f, gru_bhh_b, feats);
    }

    // semantic net
    gemm_tn<true><<<dim3(4096 / 64, 1), 256>>>(batch_attrs, A_, fc1_w, A_, fc1_b,
                                               attr1, 4096, C, 4096, A_);
    gemm_tn<true><<<dim3(512 / 64, 1), 256>>>(attr1, 4096, fc2_w, 4096, fc2_b,
                                              attr2, 512, C, 512, 4096);

    // relation head (tensor cores, fused)
    {
        int smem = REL_SMEM_FLOATS * (int)sizeof(float);
        cudaFuncSetAttribute(relation_mma, cudaFuncAttributeMaxDynamicSharedMemorySize, smem);
        relation_mma<<<dim3(C / 2, B), 256, smem>>>(feats, attr2, fc3_w, fc3_b,
                                                    fc4_w, fc4_b, logits);
    }

    softmax_colreduce<<<T, 256>>>(logits, cmax, csum);
    softmax_out<<<(B * C + 255) / 256, 256>>>(logits, cmax, csum, out);
}

// round 5
// speedup vs baseline: 1.9443x; 1.1787x over previous
#include <cuda_runtime.h>
#include <math.h>
#include <stdint.h>

#define B    64
#define T    32
#define D    4096
#define C    50
#define A_   300
#define H    256
#define GI_W 1536

// ---------------------------------------------------------------------------
// Scratch
// ---------------------------------------------------------------------------
__device__ float g_GI[B * T * GI_W];
__device__ float g_feats[B * T * 512];
__device__ float g_attr1[C * 4096];
__device__ float g_attr2[C * 512];
__device__ float g_logits[B * C * T];
__device__ float g_cmax[T];
__device__ float g_csum[T];
__device__ float g_hbuf[2 * 2 * B * H];
__device__ float g_wih_pack[GI_W * D];
__device__ float g_bih_pack[GI_W];
__device__ float g_w3h[256 * 512];
__device__ float g_w3l[256 * 512];
__device__ float g_fc2part[4 * 64 * 512];
__device__ int   g_rmin[B * T];
__device__ int   g_rmout[B * T];
__device__ int   g_count[B];
__device__ int   g_mnz[1];
__device__ int          g_bar_count;
__device__ unsigned int g_bar_gen;

// ---------------------------------------------------------------------------
// tf32 / sync helpers
// ---------------------------------------------------------------------------
__device__ __forceinline__ void mma8(float* c, const uint32_t* a, const uint32_t* b)
{
    asm volatile(
        "mma.sync.aligned.m16n8k8.row.col.f32.tf32.tf32.f32 "
        "{%0,%1,%2,%3},{%4,%5,%6,%7},{%8,%9},{%0,%1,%2,%3};"
        : "+f"(c[0]), "+f"(c[1]), "+f"(c[2]), "+f"(c[3])
        : "r"(a[0]), "r"(a[1]), "r"(a[2]), "r"(a[3]), "r"(b[0]), "r"(b[1]));
}

__device__ __forceinline__ void split1(float v, float& h, float& l)
{
    uint32_t u;
    asm("cvt.rna.tf32.f32 %0, %1;" : "=r"(u) : "f"(v));
    h = __uint_as_float(u);
    l = v - h;
}
__device__ __forceinline__ void split4(float4 v, float4& h, float4& l)
{
    split1(v.x, h.x, l.x); split1(v.y, h.y, l.y);
    split1(v.z, h.z, l.z); split1(v.w, h.w, l.w);
}

__device__ __forceinline__ unsigned ld_acq(const unsigned* p)
{
    unsigned v;
    asm volatile("ld.acquire.gpu.u32 %0,[%1];" : "=r"(v) : "l"(p) : "memory");
    return v;
}
__device__ __forceinline__ void st_rel(unsigned* p, unsigned v)
{
    asm volatile("st.release.gpu.u32 [%0],%1;" :: "l"(p), "r"(v) : "memory");
}

// ---------------------------------------------------------------------------
// 0a) Pack GRU input weights/biases
// ---------------------------------------------------------------------------
__global__ __launch_bounds__(256) void pack_wih(
    const float* __restrict__ wf, const float* __restrict__ wb,
    const float* __restrict__ bf, const float* __restrict__ bb,
    float* __restrict__ wp, float* __restrict__ bp)
{
    int i = blockIdx.x * 256 + threadIdx.x;
    const int TOT4 = GI_W * D / 4;
    if (i < TOT4) {
        int row = (i * 4) / D;
        float4 v;
        if (row < 768) v = ((const float4*)wf)[i];
        else           v = ((const float4*)wb)[i - 768 * D / 4];
        ((float4*)wp)[i] = v;
    }
    if (i < GI_W) bp[i] = (i < 768) ? bf[i] : bb[i - 768];
}

// 0b) Pre-split w3 into tf32 hi/lo
__global__ __launch_bounds__(256) void split_w3(
    const float* __restrict__ w3, float* __restrict__ hh, float* __restrict__ ll)
{
    int i = blockIdx.x * 256 + threadIdx.x;
    if (i < 256 * 512) {
        float h, l;
        split1(w3[i], h, l);
        hh[i] = h; ll[i] = l;
    }
}

// ---------------------------------------------------------------------------
// 1) Bookkeeping: per-batch order, counts, compacted row maps
// ---------------------------------------------------------------------------
__global__ void build_maps(
    const float* __restrict__ att,
    int* __restrict__ rmin, int* __restrict__ rmout,
    int* __restrict__ count, int* __restrict__ mnz)
{
    __shared__ int cnts[B], offs[B];
    int b = threadIdx.x;   // 64 threads
    float a[T];
    float s = 0.f;
#pragma unroll
    for (int t = 0; t < T; t++) { a[t] = att[b * T + t]; s += a[t]; }
    float thr = s / (float)T;
    int ord[T];
    int c = 0;
#pragma unroll
    for (int t = 0; t < T; t++) if (a[t] >= thr) ord[c++] = t;
    cnts[b] = c;
    __syncthreads();
    if (b == 0) {
        int acc = 0;
        for (int i = 0; i < B; i++) { offs[i] = acc; acc += cnts[i]; }
        *mnz = acc;
    }
    __syncthreads();
    int o = offs[b];
    for (int s2 = 0; s2 < c; s2++) {
        rmin[o + s2]  = b * T + ord[s2];
        rmout[o + s2] = b * T + s2;
    }
    count[b] = c;
}

// ---------------------------------------------------------------------------
// 2) GI projection, tensor cores, 3xTF32, gather via rowmap, zero-row skip.
// ---------------------------------------------------------------------------
__global__ __launch_bounds__(256, 2) void gemm_mma_gi(
    const float* __restrict__ A,
    const float* __restrict__ W,
    const float* __restrict__ bias,
    float* __restrict__ Cg,
    const int* __restrict__ rmin,
    const int* __restrict__ rmout,
    const int* __restrict__ mnzp)
{
    int Mnz = *mnzp;
    int row0 = blockIdx.y * 128, col0 = blockIdx.x * 64;
    if (row0 >= Mnz) return;

    __shared__ float Ah[128][20], Al[128][20], Wh[64][20], Wl[64][20];
    int tid  = threadIdx.x;
    int lane = tid & 31, warp = tid >> 5;
    int wm = warp >> 1, wn = warp & 1;
    int g  = lane >> 2, tg = lane & 3;

    float c[2][4][4];
#pragma unroll
    for (int mt = 0; mt < 2; mt++)
#pragma unroll
        for (int nt = 0; nt < 4; nt++)
#pragma unroll
            for (int r = 0; r < 4; r++) c[mt][nt][r] = 0.f;

    int lr = tid >> 1;
    int lk = (tid & 1) * 8;
    int m  = row0 + lr;
    bool av = (m < Mnz);
    const float* asrc = A + (size_t)(av ? rmin[m] : 0) * D;

    for (int k0 = 0; k0 < D; k0 += 16) {
        {
            float4 v0 = make_float4(0.f, 0.f, 0.f, 0.f), v1 = v0;
            if (av) {
                v0 = *(const float4*)(asrc + k0 + lk);
                v1 = *(const float4*)(asrc + k0 + lk + 4);
            }
            float4 h, l;
            split4(v0, h, l);
            *(float4*)&Ah[lr][lk] = h; *(float4*)&Al[lr][lk] = l;
            split4(v1, h, l);
            *(float4*)&Ah[lr][lk + 4] = h; *(float4*)&Al[lr][lk + 4] = l;
        }
        if (tid < 128) {
            int wr = tid >> 1;
            const float* src = W + (size_t)(col0 + wr) * D + k0 + lk;
            float4 v0 = *(const float4*)src;
            float4 v1 = *(const float4*)(src + 4);
            float4 h, l;
            split4(v0, h, l);
            *(float4*)&Wh[wr][lk] = h; *(float4*)&Wl[wr][lk] = l;
            split4(v1, h, l);
            *(float4*)&Wh[wr][lk + 4] = h; *(float4*)&Wl[wr][lk + 4] = l;
        }
        __syncthreads();

#pragma unroll
        for (int ks = 0; ks < 2; ks++) {
            int kb = ks * 8;
            uint32_t ah[2][4], al[2][4];
#pragma unroll
            for (int mt = 0; mt < 2; mt++) {
                int m0 = wm * 32 + mt * 16;
                ah[mt][0] = __float_as_uint(Ah[m0 + g][kb + tg]);
                ah[mt][1] = __float_as_uint(Ah[m0 + g + 8][kb + tg]);
                ah[mt][2] = __float_as_uint(Ah[m0 + g][kb + tg + 4]);
                ah[mt][3] = __float_as_uint(Ah[m0 + g + 8][kb + tg + 4]);
                al[mt][0] = __float_as_uint(Al[m0 + g][kb + tg]);
                al[mt][1] = __float_as_uint(Al[m0 + g + 8][kb + tg]);
                al[mt][2] = __float_as_uint(Al[m0 + g][kb + tg + 4]);
                al[mt][3] = __float_as_uint(Al[m0 + g + 8][kb + tg + 4]);
            }
#pragma unroll
            for (int nt = 0; nt < 4; nt++) {
                int n0 = wn * 32 + nt * 8;
                uint32_t bh[2], bl[2];
                bh[0] = __float_as_uint(Wh[n0 + g][kb + tg]);
                bh[1] = __float_as_uint(Wh[n0 + g][kb + tg + 4]);
                bl[0] = __float_as_uint(Wl[n0 + g][kb + tg]);
                bl[1] = __float_as_uint(Wl[n0 + g][kb + tg + 4]);
#pragma unroll
                for (int mt = 0; mt < 2; mt++) {
                    mma8(c[mt][nt], ah[mt], bh);
                    mma8(c[mt][nt], al[mt], bh);
                    mma8(c[mt][nt], ah[mt], bl);
                }
            }
        }
        __syncthreads();
    }

#pragma unroll
    for (int mt = 0; mt < 2; mt++) {
        int mrow1 = row0 + wm * 32 + mt * 16 + g;
        int mrow2 = mrow1 + 8;
        int ro1 = (mrow1 < Mnz) ? rmout[mrow1] : -1;
        int ro2 = (mrow2 < Mnz) ? rmout[mrow2] : -1;
#pragma unroll
        for (int nt = 0; nt < 4; nt++) {
            int col = col0 + wn * 32 + nt * 8 + 2 * tg;
            float b0 = bias[col], b1 = bias[col + 1];
            if (ro1 >= 0)
                *(float2*)(Cg + (size_t)ro1 * GI_W + col) =
                    make_float2(c[mt][nt][0] + b0, c[mt][nt][1] + b1);
            if (ro2 >= 0)
                *(float2*)(Cg + (size_t)ro2 * GI_W + col) =
                    make_float2(c[mt][nt][2] + b0, c[mt][nt][3] + b1);
        }
    }
}

// ---------------------------------------------------------------------------
// 2b) Small-M GEMM (fc1) and fc2 K-split
// ---------------------------------------------------------------------------
template <bool RELU>
__global__ __launch_bounds__(256) void gemm_tn(
    const float* __restrict__ Ag, int lda,
    const float* __restrict__ Wg, int ldw,
    const float* __restrict__ bias,
    float* __restrict__ Cg, int ldc,
    int M, int N, int K)
{
    __shared__ float As[16][65];
    __shared__ float Ws[16][65];
    int tid  = threadIdx.x;
    int row0 = blockIdx.y * 64;
    int col0 = blockIdx.x * 64;
    int lm = tid >> 2;
    int lk = (tid & 3) * 4;
    int ty = tid >> 4;
    int tx = tid & 15;
    float acc[4][4];
#pragma unroll
    for (int i = 0; i < 4; i++)
#pragma unroll
        for (int j = 0; j < 4; j++) acc[i][j] = 0.f;

    for (int k0 = 0; k0 < K; k0 += 16) {
        int r = row0 + lm;
        int cc = col0 + lm;
#pragma unroll
        for (int i = 0; i < 4; i++) {
            int k = k0 + lk + i;
            As[lk + i][lm] = (r < M && k < K) ? Ag[(size_t)r * lda + k] : 0.f;
            Ws[lk + i][lm] = (cc < N && k < K) ? Wg[(size_t)cc * ldw + k] : 0.f;
        }
        __syncthreads();
#pragma unroll
        for (int kk = 0; kk < 16; kk++) {
            float a[4], w[4];
#pragma unroll
            for (int i = 0; i < 4; i++) a[i] = As[kk][ty + 16 * i];
#pragma unroll
            for (int j = 0; j < 4; j++) w[j] = Ws[kk][tx + 16 * j];
#pragma unroll
            for (int i = 0; i < 4; i++)
#pragma unroll
                for (int j = 0; j < 4; j++)
                    acc[i][j] = fmaf(a[i], w[j], acc[i][j]);
        }
        __syncthreads();
    }

#pragma unroll
    for (int i = 0; i < 4; i++) {
        int r = row0 + ty + 16 * i;
        if (r >= M) continue;
#pragma unroll
        for (int j = 0; j < 4; j++) {
            int cc = col0 + tx + 16 * j;
            if (cc >= N) continue;
            float v = acc[i][j] + bias[cc];
            if (RELU) v = fmaxf(v, 0.f);
            Cg[(size_t)r * ldc + cc] = v;
        }
    }
}

// fc2 partials: grid (8 n-blocks, 4 k-chunks). M=50, N=512, Kchunk=1024.
__global__ __launch_bounds__(256) void fc2_part(
    const float* __restrict__ Ag,
    const float* __restrict__ Wg,
    float* __restrict__ Pout)
{
    __shared__ float As[16][65];
    __shared__ float Ws[16][65];
    int tid  = threadIdx.x;
    int col0 = blockIdx.x * 64;
    int kbeg = blockIdx.y * 1024;
    int lm = tid >> 2;
    int lk = (tid & 3) * 4;
    int ty = tid >> 4;
    int tx = tid & 15;
    float acc[4][4];
#pragma unroll
    for (int i = 0; i < 4; i++)
#pragma unroll
        for (int j = 0; j < 4; j++) acc[i][j] = 0.f;

    for (int k0 = kbeg; k0 < kbeg + 1024; k0 += 16) {
        int cc = col0 + lm;
#pragma unroll
        for (int i = 0; i < 4; i++) {
            int k = k0 + lk + i;
            As[lk + i][lm] = (lm < C) ? Ag[(size_t)lm * 4096 + k] : 0.f;
            Ws[lk + i][lm] = Wg[(size_t)cc * 4096 + k];
        }
        __syncthreads();
#pragma unroll
        for (int kk = 0; kk < 16; kk++) {
            float a[4], w[4];
#pragma unroll
            for (int i = 0; i < 4; i++) a[i] = As[kk][ty + 16 * i];
#pragma unroll
            for (int j = 0; j < 4; j++) w[j] = Ws[kk][tx + 16 * j];
#pragma unroll
            for (int i = 0; i < 4; i++)
#pragma unroll
                for (int j = 0; j < 4; j++)
                    acc[i][j] = fmaf(a[i], w[j], acc[i][j]);
        }
        __syncthreads();
    }

    float* base = Pout + (size_t)blockIdx.y * (64 * 512);
#pragma unroll
    for (int i = 0; i < 4; i++) {
        int r = ty + 16 * i;
        if (r >= C) continue;
#pragma unroll
        for (int j = 0; j < 4; j++) {
            int cc = col0 + tx + 16 * j;
            base[(size_t)r * 512 + cc] = acc[i][j];
        }
    }
}

__global__ __launch_bounds__(256) void fc2_reduce(
    const float* __restrict__ P, const float* __restrict__ bias,
    float* __restrict__ attr2)
{
    int idx = blockIdx.x * 256 + threadIdx.x;
    if (idx < C * 512) {
        int r = idx >> 9, cc = idx & 511;
        float v = bias[cc];
#pragma unroll
        for (int kc = 0; kc < 4; kc++)
            v += P[(size_t)kc * (64 * 512) + r * 512 + cc];
        attr2[idx] = fmaxf(v, 0.f);
    }
}

// ---------------------------------------------------------------------------
// 3) GRU recurrence: persistent, acquire/release barrier WITH nanosleep yield
// ---------------------------------------------------------------------------
#define GRU_BLOCKS 128

__device__ __forceinline__ void grid_barrier()
{
    __syncthreads();
    if (threadIdx.x == 0) {
        __threadfence();   // release my h stores
        unsigned g = ld_acq(&g_bar_gen);
        if (atomicAdd(&g_bar_count, 1) == GRU_BLOCKS - 1) {
            g_bar_count = 0;
            st_rel(&g_bar_gen, g + 1);
        } else {
            while (ld_acq(&g_bar_gen) == g) { __nanosleep(16); }
        }
    }
    __syncthreads();
}

__global__ __launch_bounds__(256) void gru_kernel(
    const float* __restrict__ GI,
    const float* __restrict__ whh_f, const float* __restrict__ whh_b,
    const float* __restrict__ bhh_f, const float* __restrict__ bhh_b,
    const float* __restrict__ bpack,
    const int*   __restrict__ count,
    float* __restrict__ feats)
{
    extern __shared__ float4 sm4[];
    float4* sW4 = sm4;
    float4* hS4 = sm4 + 12 * 65;

    int d  = blockIdx.x >> 6;
    int hc = blockIdx.x & 63;
    int tid = threadIdx.x;
    int b = tid >> 2;
    int u = tid & 3;
    int i = hc * 4 + u;

    const float* whh = d ? whh_b : whh_f;
    const float* bhh = d ? bhh_b : bhh_f;

    for (int t = tid; t < 12 * 64; t += 256) {
        int rr = t >> 6;
        int k4 = t & 63;
        int g  = rr >> 2, uu = rr & 3;
        int row = g * H + hc * 4 + uu;
        sW4[rr * 65 + k4] = ((const float4*)(whh + (size_t)row * H))[k4];
    }
    float br = bhh[i], bz = bhh[H + i], bn = bhh[2 * H + i];
    float ir0 = bpack[d * 768 + i];
    float iz0 = bpack[d * 768 + 256 + i];
    float in0 = bpack[d * 768 + 512 + i];
    int cnt_b = count[b];
    __syncthreads();

    float h = 0.f;

    for (int t = 0; t < T; t++) {
        float ar = 0.f, az = 0.f, an = 0.f;
        if (t > 0) {
            int p = t & 1;
            const float4* hp4 = (const float4*)(g_hbuf + p * (2 * B * H) + d * (B * H));
            for (int idx = tid; idx < B * (H / 4); idx += 256)
                hS4[(idx >> 6) * 65 + (idx & 63)] = __ldcg(&hp4[idx]);
            __syncthreads();

            const float4* hb = &hS4[b * 65];
            const float4* wr = &sW4[(0 + u) * 65];
            const float4* wz = &sW4[(4 + u) * 65];
            const float4* wn = &sW4[(8 + u) * 65];
#pragma unroll 16
            for (int k4 = 0; k4 < 64; k4++) {
                float4 hv = hb[k4];
                float4 a  = wr[k4];
                ar = fmaf(hv.x, a.x, fmaf(hv.y, a.y, fmaf(hv.z, a.z, fmaf(hv.w, a.w, ar))));
                float4 zz = wz[k4];
                az = fmaf(hv.x, zz.x, fmaf(hv.y, zz.y, fmaf(hv.z, zz.z, fmaf(hv.w, zz.w, az))));
                float4 nn = wn[k4];
                an = fmaf(hv.x, nn.x, fmaf(hv.y, nn.y, fmaf(hv.z, nn.z, fmaf(hv.w, nn.w, an))));
            }
        }

        int s = d ? (T - 1 - t) : t;
        float ir = ir0, iz = iz0, in_ = in0;
        if (s < cnt_b) {
            const float* gi = GI + ((size_t)b * T + s) * GI_W + d * 768;
            ir  = gi[i];
            iz  = gi[H + i];
            in_ = gi[2 * H + i];
        }

        float r = 1.f / (1.f + expf(-(ir + ar + br)));
        float z = 1.f / (1.f + expf(-(iz + az + bz)));
        float n = tanhf(in_ + r * (an + bn));
        h = (1.f - z) * n + z * h;

        feats[((size_t)b * T + s) * 512 + d * H + i] = h;
        if (t < T - 1) {
            g_hbuf[((t & 1) ^ 1) * (2 * B * H) + d * (B * H) + b * H + i] = h;
            grid_barrier();
        }
    }
}

// ---------------------------------------------------------------------------
// 4) Relation head, tensor cores, pre-split w3
// ---------------------------------------------------------------------------
#define REL_SMEM_FLOATS (64*20*2 + 256*20*2 + 2*512 + 64*5)

__global__ __launch_bounds__(256, 2) void relation_mma(
    const float* __restrict__ feats,
    const float* __restrict__ attr2,
    const float* __restrict__ w3h,
    const float* __restrict__ w3l,
    const float* __restrict__ b3,
    const float* __restrict__ w4,
    const float* __restrict__ b4,
    float* __restrict__ logits)
{
    extern __shared__ float smemR[];
    float (*Dh)[20] = (float(*)[20])(smemR);
    float (*Dl)[20] = (float(*)[20])(smemR + 64 * 20);
    float (*Wh)[20] = (float(*)[20])(smemR + 64 * 20 * 2);
    float (*Wl)[20] = (float(*)[20])(smemR + 64 * 20 * 2 + 256 * 20);
    float* aS       = smemR + 64 * 20 * 2 + 256 * 20 * 2;
    float (*part)[5]= (float(*)[5])(aS + 2 * 512);

    int c0 = blockIdx.x * 2;
    int b  = blockIdx.y;
    int tid  = threadIdx.x;
    int lane = tid & 31, warp = tid >> 5;
    int wm = warp >> 2, wn = warp & 3;
    int g  = lane >> 2, tg = lane & 3;

    for (int t = tid; t < 1024; t += 256)
        aS[t] = attr2[(size_t)(c0 + (t >> 9)) * 512 + (t & 511)];
    __syncthreads();

    float c[2][8][4];
#pragma unroll
    for (int mt = 0; mt < 2; mt++)
#pragma unroll
        for (int nt = 0; nt < 8; nt++)
#pragma unroll
            for (int r = 0; r < 4; r++) c[mt][nt][r] = 0.f;

    int dm = tid >> 2;
    int dk = (tid & 3) * 4;
    int ds = dm & 31, dc = dm >> 5;
    const float* frow = feats + ((size_t)b * T + ds) * 512;

    for (int k0 = 0; k0 < 512; k0 += 16) {
        {
            float4 f = *(const float4*)(frow + k0 + dk);
            float4 a = *(const float4*)(aS + dc * 512 + k0 + dk);
            float4 dd;
            dd.x = (f.x - a.x) * (f.x - a.x);
            dd.y = (f.y - a.y) * (f.y - a.y);
            dd.z = (f.z - a.z) * (f.z - a.z);
            dd.w = (f.w - a.w) * (f.w - a.w);
            float4 h, l;
            split4(dd, h, l);
            *(float4*)&Dh[dm][dk] = h;
            *(float4*)&Dl[dm][dk] = l;
        }
        {
            const float4* whp = (const float4*)(w3h + (size_t)tid * 512 + k0);
            const float4* wlp = (const float4*)(w3l + (size_t)tid * 512 + k0);
#pragma unroll
            for (int q = 0; q < 4; q++) {
                *(float4*)&Wh[tid][q * 4] = whp[q];
                *(float4*)&Wl[tid][q * 4] = wlp[q];
            }
        }
        __syncthreads();

#pragma unroll
        for (int ks = 0; ks < 2; ks++) {
            int kb = ks * 8;
            uint32_t ah[2][4], al[2][4];
#pragma unroll
            for (int mt = 0; mt < 2; mt++) {
                int m0 = wm * 32 + mt * 16;
                ah[mt][0] = __float_as_uint(Dh[m0 + g][kb + tg]);
                ah[mt][1] = __float_as_uint(Dh[m0 + g + 8][kb + tg]);
                ah[mt][2] = __float_as_uint(Dh[m0 + g][kb + tg + 4]);
                ah[mt][3] = __float_as_uint(Dh[m0 + g + 8][kb + tg + 4]);
                al[mt][0] = __float_as_uint(Dl[m0 + g][kb + tg]);
                al[mt][1] = __float_as_uint(Dl[m0 + g + 8][kb + tg]);
                al[mt][2] = __float_as_uint(Dl[m0 + g][kb + tg + 4]);
                al[mt][3] = __float_as_uint(Dl[m0 + g + 8][kb + tg + 4]);
            }
#pragma unroll
            for (int nt = 0; nt < 8; nt++) {
                int n0 = wn * 64 + nt * 8;
                uint32_t bh[2], bl[2];
                bh[0] = __float_as_uint(Wh[n0 + g][kb + tg]);
                bh[1] = __float_as_uint(Wh[n0 + g][kb + tg + 4]);
                bl[0] = __float_as_uint(Wl[n0 + g][kb + tg]);
                bl[1] = __float_as_uint(Wl[n0 + g][kb + tg + 4]);
#pragma unroll
                for (int mt = 0; mt < 2; mt++) {
                    mma8(c[mt][nt], ah[mt], bh);
                    mma8(c[mt][nt], al[mt], bh);
                    mma8(c[mt][nt], ah[mt], bl);
                }
            }
        }
        __syncthreads();
    }

    float rs[2][2] = {{0.f, 0.f}, {0.f, 0.f}};
#pragma unroll
    for (int nt = 0; nt < 8; nt++) {
        int col = wn * 64 + nt * 8 + 2 * tg;
        float w40 = w4[col], w41 = w4[col + 1];
        float b30 = b3[col], b31 = b3[col + 1];
#pragma unroll
        for (int mt = 0; mt < 2; mt++) {
            rs[mt][0] += fmaxf(c[mt][nt][0] + b30, 0.f) * w40
                       + fmaxf(c[mt][nt][1] + b31, 0.f) * w41;
            rs[mt][1] += fmaxf(c[mt][nt][2] + b30, 0.f) * w40
                       + fmaxf(c[mt][nt][3] + b31, 0.f) * w41;
        }
    }
#pragma unroll
    for (int mt = 0; mt < 2; mt++)
#pragma unroll
        for (int hf = 0; hf < 2; hf++) {
            float v = rs[mt][hf];
            v += __shfl_xor_sync(0xffffffffu, v, 1);
            v += __shfl_xor_sync(0xffffffffu, v, 2);
            if (tg == 0)
                part[wm * 32 + mt * 16 + g + hf * 8][wn] = v;
        }
    __syncthreads();
    if (tid < 64) {
        float s = b4[0] + part[tid][0] + part[tid][1] + part[tid][2] + part[tid][3];
        int cc = c0 + (tid >> 5), ss = tid & 31;
        logits[((size_t)b * C + cc) * T + ss] = s;
    }
}

// ---------------------------------------------------------------------------
// 5) Softmax over dim-0 per column, mean over columns
// ---------------------------------------------------------------------------
__global__ __launch_bounds__(256) void softmax_colreduce(
    const float* __restrict__ logits, float* __restrict__ cmax, float* __restrict__ csum)
{
    int t = blockIdx.x;
    int tid = threadIdx.x;
    __shared__ float red[256];
    float m = -1e30f;
    for (int i = tid; i < B * C; i += 256) m = fmaxf(m, logits[(size_t)i * T + t]);
    red[tid] = m; __syncthreads();
    for (int s = 128; s > 0; s >>= 1) {
        if (tid < s) red[tid] = fmaxf(red[tid], red[tid + s]);
        __syncthreads();
    }
    float mx = red[0];
    __syncthreads();
    float sum = 0.f;
    for (int i = tid; i < B * C; i += 256) sum += expf(logits[(size_t)i * T + t] - mx);
    red[tid] = sum; __syncthreads();
    for (int s = 128; s > 0; s >>= 1) {
        if (tid < s) red[tid] += red[tid + s];
        __syncthreads();
    }
    if (tid == 0) { cmax[t] = mx; csum[t] = red[0]; }
}

__global__ __launch_bounds__(256) void softmax_out(
    const float* __restrict__ logits, const float* __restrict__ cmax,
    const float* __restrict__ csum, float* __restrict__ out)
{
    __shared__ float mS[T], sS[T];
    int tid = threadIdx.x;
    if (tid < T) { mS[tid] = cmax[tid]; sS[tid] = csum[tid]; }
    __syncthreads();
    int i = blockIdx.x * 256 + tid;
    if (i < B * C) {
        float a = 0.f;
        const float* row = logits + (size_t)i * T;
#pragma unroll
        for (int t = 0; t < T; t++) a += expf(row[t] - mS[t]) / sS[t];
        out[i] = a * (1.f / (float)T);
    }
}

// ---------------------------------------------------------------------------
// Launch
// ---------------------------------------------------------------------------
extern "C" void kernel_launch(void* const* d_in, const int* in_sizes, int n_in,
                              void* d_out, int out_size)
{
    const float* batch_features  = (const float*)d_in[0];
    const float* batch_att       = (const float*)d_in[1];
    const float* batch_attrs     = (const float*)d_in[2];
    const float* fc1_w = (const float*)d_in[3];
    const float* fc1_b = (const float*)d_in[4];
    const float* fc2_w = (const float*)d_in[5];
    const float* fc2_b = (const float*)d_in[6];
    const float* fc3_w = (const float*)d_in[7];
    const float* fc3_b = (const float*)d_in[8];
    const float* fc4_w = (const float*)d_in[9];
    const float* fc4_b = (const float*)d_in[10];
    const float* gru_wih_f = (const float*)d_in[11];
    const float* gru_whh_f = (const float*)d_in[12];
    const float* gru_bih_f = (const float*)d_in[13];
    const float* gru_bhh_f = (const float*)d_in[14];
    const float* gru_wih_b = (const float*)d_in[15];
    const float* gru_whh_b = (const float*)d_in[16];
    const float* gru_bih_b = (const float*)d_in[17];
    const float* gru_bhh_b = (const float*)d_in[18];
    float* out = (float*)d_out;

    float* GI;     cudaGetSymbolAddress((void**)&GI,     g_GI);
    float* feats;  cudaGetSymbolAddress((void**)&feats,  g_feats);
    float* attr1;  cudaGetSymbolAddress((void**)&attr1,  g_attr1);
    float* attr2;  cudaGetSymbolAddress((void**)&attr2,  g_attr2);
    float* logits; cudaGetSymbolAddress((void**)&logits, g_logits);
    float* cmax;   cudaGetSymbolAddress((void**)&cmax,   g_cmax);
    float* csum;   cudaGetSymbolAddress((void**)&csum,   g_csum);
    float* wpack;  cudaGetSymbolAddress((void**)&wpack,  g_wih_pack);
    float* bpack;  cudaGetSymbolAddress((void**)&bpack,  g_bih_pack);
    float* w3h;    cudaGetSymbolAddress((void**)&w3h,    g_w3h);
    float* w3l;    cudaGetSymbolAddress((void**)&w3l,    g_w3l);
    float* fc2p;   cudaGetSymbolAddress((void**)&fc2p,   g_fc2part);
    int* rmin;     cudaGetSymbolAddress((void**)&rmin,   g_rmin);
    int* rmout;    cudaGetSymbolAddress((void**)&rmout,  g_rmout);
    int* cnt;      cudaGetSymbolAddress((void**)&cnt,    g_count);
    int* mnz;      cudaGetSymbolAddress((void**)&mnz,    g_mnz);

    build_maps<<<1, 64>>>(batch_att, rmin, rmout, cnt, mnz);
    pack_wih<<<(GI_W * D / 4 + 255) / 256, 256>>>(gru_wih_f, gru_wih_b,
                                                  gru_bih_f, gru_bih_b, wpack, bpack);
    split_w3<<<(256 * 512 + 255) / 256, 256>>>(fc3_w, w3h, w3l);

    // GI projection (tensor cores, compacted rows)
    {
        dim3 grid(GI_W / 64, (B * T) / 128);   // (24, 16); ~half exit early
        gemm_mma_gi<<<grid, 256>>>(batch_features, wpack, bpack, GI, rmin, rmout, mnz);
    }

    // GRU recurrence
    {
        int smem = (12 * 65 + 64 * 65) * (int)sizeof(float4);
        cudaFuncSetAttribute(gru_kernel, cudaFuncAttributeMaxDynamicSharedMemorySize, smem);
        gru_kernel<<<GRU_BLOCKS, 256, smem>>>(GI, gru_whh_f, gru_whh_b,
                                              gru_bhh_f, gru_bhh_b, bpack, cnt, feats);
    }

    // semantic net
    gemm_tn<true><<<dim3(4096 / 64, 1), 256>>>(batch_attrs, A_, fc1_w, A_, fc1_b,
                                               attr1, 4096, C, 4096, A_);
    fc2_part<<<dim3(8, 4), 256>>>(attr1, fc2_w, fc2p);
    fc2_reduce<<<(C * 512 + 255) / 256, 256>>>(fc2p, fc2_b, attr2);

    // relation head
    {
        int smem = REL_SMEM_FLOATS * (int)sizeof(float);
        cudaFuncSetAttribute(relation_mma, cudaFuncAttributeMaxDynamicSharedMemorySize, smem);
        relation_mma<<<dim3(C / 2, B), 256, smem>>>(feats, attr2, w3h, w3l,
                                                    fc3_b, fc4_w, fc4_b, logits);
    }

    softmax_colreduce<<<T, 256>>>(logits, cmax, csum);
    softmax_out<<<(B * C + 255) / 256, 256>>>(logits, cmax, csum, out);
}

// round 8
// speedup vs baseline: 2.5279x; 1.3002x over previous
#include <cuda_runtime.h>
#include <cuda_bf16.h>
#include <math.h>
#include <stdint.h>

#define B    64
#define T    32
#define D    4096
#define C    50
#define A_   300
#define H    256
#define GI_W 1536

// ---------------------------------------------------------------------------
// Scratch
// ---------------------------------------------------------------------------
__device__ float g_GI[B * T * GI_W];
__device__ float g_feats[B * T * 512];
__device__ float g_attr1[C * 4096];
__device__ float g_attr2[C * 512];
__device__ float g_logits[B * C * T];
__device__ float g_cmax[T];
__device__ float g_csum[T];
__device__ float g_hbuf[2 * 2 * B * H];
__device__ float g_wih_pack[GI_W * D];
__device__ float g_bih_pack[GI_W];
__device__ __nv_bfloat16 g_w3hi[256 * 512];
__device__ __nv_bfloat16 g_w3lo[256 * 512];
__device__ float g_fc2part[4 * 64 * 512];
__device__ int   g_rmin[B * T];
__device__ int   g_rmout[B * T];
__device__ int   g_count[B];
__device__ int   g_mnz[1];
__device__ int          g_bar_count;
__device__ unsigned int g_bar_gen;

// ---------------------------------------------------------------------------
// tf32 / bf16 / sync helpers
// ---------------------------------------------------------------------------
__device__ __forceinline__ void mma8(float* c, const uint32_t* a, const uint32_t* b)
{
    asm volatile(
        "mma.sync.aligned.m16n8k8.row.col.f32.tf32.tf32.f32 "
        "{%0,%1,%2,%3},{%4,%5,%6,%7},{%8,%9},{%0,%1,%2,%3};"
        : "+f"(c[0]), "+f"(c[1]), "+f"(c[2]), "+f"(c[3])
        : "r"(a[0]), "r"(a[1]), "r"(a[2]), "r"(a[3]), "r"(b[0]), "r"(b[1]));
}

__device__ __forceinline__ void mma16(float* c, const uint32_t* a, const uint32_t* b)
{
    asm volatile(
        "mma.sync.aligned.m16n8k16.row.col.f32.bf16.bf16.f32 "
        "{%0,%1,%2,%3},{%4,%5,%6,%7},{%8,%9},{%0,%1,%2,%3};"
        : "+f"(c[0]), "+f"(c[1]), "+f"(c[2]), "+f"(c[3])
        : "r"(a[0]), "r"(a[1]), "r"(a[2]), "r"(a[3]), "r"(b[0]), "r"(b[1]));
}

__device__ __forceinline__ void split1(float v, float& h, float& l)
{
    uint32_t u;
    asm("cvt.rna.tf32.f32 %0, %1;" : "=r"(u) : "f"(v));
    h = __uint_as_float(u);
    l = v - h;
}
__device__ __forceinline__ void split4(float4 v, float4& h, float4& l)
{
    split1(v.x, h.x, l.x); split1(v.y, h.y, l.y);
    split1(v.z, h.z, l.z); split1(v.w, h.w, l.w);
}

// split two floats into bf16 hi pair + bf16 lo-residual pair (packed uint32)
__device__ __forceinline__ void bsplit2(float x, float y, uint32_t& hw, uint32_t& lw)
{
    __nv_bfloat16 hx = __float2bfloat16(x);
    __nv_bfloat16 hy = __float2bfloat16(y);
    float rx = x - __bfloat162float(hx);
    float ry = y - __bfloat162float(hy);
    __nv_bfloat162 hp; hp.x = hx; hp.y = hy;
    __nv_bfloat162 lp; lp.x = __float2bfloat16(rx); lp.y = __float2bfloat16(ry);
    hw = *reinterpret_cast<uint32_t*>(&hp);
    lw = *reinterpret_cast<uint32_t*>(&lp);
}

__device__ __forceinline__ unsigned ld_acq(const unsigned* p)
{
    unsigned v;
    asm volatile("ld.acquire.gpu.u32 %0,[%1];" : "=r"(v) : "l"(p) : "memory");
    return v;
}
__device__ __forceinline__ void st_rel(unsigned* p, unsigned v)
{
    asm volatile("st.release.gpu.u32 [%0],%1;" :: "l"(p), "r"(v) : "memory");
}

// ---------------------------------------------------------------------------
// 0a) Pack GRU input weights/biases (fp32, round-5 proven)
// ---------------------------------------------------------------------------
__global__ __launch_bounds__(256) void pack_wih(
    const float* __restrict__ wf, const float* __restrict__ wb,
    const float* __restrict__ bf, const float* __restrict__ bb,
    float* __restrict__ wp, float* __restrict__ bp)
{
    int i = blockIdx.x * 256 + threadIdx.x;
    const int TOT4 = GI_W * D / 4;
    if (i < TOT4) {
        int row = (i * 4) / D;
        float4 v;
        if (row < 768) v = ((const float4*)wf)[i];
        else           v = ((const float4*)wb)[i - 768 * (D / 4)];
        ((float4*)wp)[i] = v;
    }
    if (i < GI_W) bp[i] = (i < 768) ? bf[i] : bb[i - 768];
}

// 0b) Pre-split w3 to bf16 hi/lo (the ONE new component this round)
__global__ __launch_bounds__(256) void split_w3_bf16(
    const float* __restrict__ w3,
    __nv_bfloat16* __restrict__ hh, __nv_bfloat16* __restrict__ ll)
{
    int i = blockIdx.x * 256 + threadIdx.x;           // pair index
    if (i < 256 * 512 / 2) {
        float2 v = ((const float2*)w3)[i];
        uint32_t h, l;
        bsplit2(v.x, v.y, h, l);
        ((uint32_t*)hh)[i] = h;
        ((uint32_t*)ll)[i] = l;
    }
}

// ---------------------------------------------------------------------------
// 1) Bookkeeping: per-batch counts, compacted row maps
// ---------------------------------------------------------------------------
__global__ void build_maps(
    const float* __restrict__ att,
    int* __restrict__ rmin, int* __restrict__ rmout,
    int* __restrict__ count, int* __restrict__ mnz)
{
    __shared__ int cnts[B], offs[B];
    int b = threadIdx.x;   // 64 threads
    float a[T];
    float s = 0.f;
#pragma unroll
    for (int t = 0; t < T; t++) { a[t] = att[b * T + t]; s += a[t]; }
    float thr = s / (float)T;
    int ord[T];
    int c = 0;
#pragma unroll
    for (int t = 0; t < T; t++) if (a[t] >= thr) ord[c++] = t;
    cnts[b] = c;
    __syncthreads();
    if (b == 0) {
        int acc = 0;
        for (int i = 0; i < B; i++) { offs[i] = acc; acc += cnts[i]; }
        *mnz = acc;
    }
    __syncthreads();
    int o = offs[b];
    for (int s2 = 0; s2 < c; s2++) {
        rmin[o + s2]  = b * T + ord[s2];
        rmout[o + s2] = b * T + s2;
    }
    count[b] = c;
}

// ---------------------------------------------------------------------------
// 2) GI projection, tensor cores, 3xTF32, gather via rowmap (round-5 proven)
// ---------------------------------------------------------------------------
__global__ __launch_bounds__(256, 2) void gemm_mma_gi(
    const float* __restrict__ A,
    const float* __restrict__ W,
    const float* __restrict__ bias,
    float* __restrict__ Cg,
    const int* __restrict__ rmin,
    const int* __restrict__ rmout,
    const int* __restrict__ mnzp)
{
    int Mnz = *mnzp;
    int row0 = blockIdx.y * 128, col0 = blockIdx.x * 64;
    if (row0 >= Mnz) return;

    __shared__ float Ah[128][20], Al[128][20], Wh[64][20], Wl[64][20];
    int tid  = threadIdx.x;
    int lane = tid & 31, warp = tid >> 5;
    int wm = warp >> 1, wn = warp & 1;
    int g  = lane >> 2, tg = lane & 3;

    float c[2][4][4];
#pragma unroll
    for (int mt = 0; mt < 2; mt++)
#pragma unroll
        for (int nt = 0; nt < 4; nt++)
#pragma unroll
            for (int r = 0; r < 4; r++) c[mt][nt][r] = 0.f;

    int lr = tid >> 1;
    int lk = (tid & 1) * 8;
    int m  = row0 + lr;
    bool av = (m < Mnz);
    const float* asrc = A + (size_t)(av ? rmin[m] : 0) * D;

    for (int k0 = 0; k0 < D; k0 += 16) {
        {
            float4 v0 = make_float4(0.f, 0.f, 0.f, 0.f), v1 = v0;
            if (av) {
                v0 = *(const float4*)(asrc + k0 + lk);
                v1 = *(const float4*)(asrc + k0 + lk + 4);
            }
            float4 h, l;
            split4(v0, h, l);
            *(float4*)&Ah[lr][lk] = h; *(float4*)&Al[lr][lk] = l;
            split4(v1, h, l);
            *(float4*)&Ah[lr][lk + 4] = h; *(float4*)&Al[lr][lk + 4] = l;
        }
        if (tid < 128) {
            int wr = tid >> 1;
            const float* src = W + (size_t)(col0 + wr) * D + k0 + lk;
            float4 v0 = *(const float4*)src;
            float4 v1 = *(const float4*)(src + 4);
            float4 h, l;
            split4(v0, h, l);
            *(float4*)&Wh[wr][lk] = h; *(float4*)&Wl[wr][lk] = l;
            split4(v1, h, l);
            *(float4*)&Wh[wr][lk + 4] = h; *(float4*)&Wl[wr][lk + 4] = l;
        }
        __syncthreads();

#pragma unroll
        for (int ks = 0; ks < 2; ks++) {
            int kb = ks * 8;
            uint32_t ah[2][4], al[2][4];
#pragma unroll
            for (int mt = 0; mt < 2; mt++) {
                int m0 = wm * 32 + mt * 16;
                ah[mt][0] = __float_as_uint(Ah[m0 + g][kb + tg]);
                ah[mt][1] = __float_as_uint(Ah[m0 + g + 8][kb + tg]);
                ah[mt][2] = __float_as_uint(Ah[m0 + g][kb + tg + 4]);
                ah[mt][3] = __float_as_uint(Ah[m0 + g + 8][kb + tg + 4]);
                al[mt][0] = __float_as_uint(Al[m0 + g][kb + tg]);
                al[mt][1] = __float_as_uint(Al[m0 + g + 8][kb + tg]);
                al[mt][2] = __float_as_uint(Al[m0 + g][kb + tg + 4]);
                al[mt][3] = __float_as_uint(Al[m0 + g + 8][kb + tg + 4]);
            }
#pragma unroll
            for (int nt = 0; nt < 4; nt++) {
                int n0 = wn * 32 + nt * 8;
                uint32_t bh[2], bl[2];
                bh[0] = __float_as_uint(Wh[n0 + g][kb + tg]);
                bh[1] = __float_as_uint(Wh[n0 + g][kb + tg + 4]);
                bl[0] = __float_as_uint(Wl[n0 + g][kb + tg]);
                bl[1] = __float_as_uint(Wl[n0 + g][kb + tg + 4]);
#pragma unroll
                for (int mt = 0; mt < 2; mt++) {
                    mma8(c[mt][nt], ah[mt], bh);
                    mma8(c[mt][nt], al[mt], bh);
                    mma8(c[mt][nt], ah[mt], bl);
                }
            }
        }
        __syncthreads();
    }

#pragma unroll
    for (int mt = 0; mt < 2; mt++) {
        int mrow1 = row0 + wm * 32 + mt * 16 + g;
        int mrow2 = mrow1 + 8;
        int ro1 = (mrow1 < Mnz) ? rmout[mrow1] : -1;
        int ro2 = (mrow2 < Mnz) ? rmout[mrow2] : -1;
#pragma unroll
        for (int nt = 0; nt < 4; nt++) {
            int col = col0 + wn * 32 + nt * 8 + 2 * tg;
            float b0 = bias[col], b1 = bias[col + 1];
            if (ro1 >= 0)
                *(float2*)(Cg + (size_t)ro1 * GI_W + col) =
                    make_float2(c[mt][nt][0] + b0, c[mt][nt][1] + b1);
            if (ro2 >= 0)
                *(float2*)(Cg + (size_t)ro2 * GI_W + col) =
                    make_float2(c[mt][nt][2] + b0, c[mt][nt][3] + b1);
        }
    }
}

// ---------------------------------------------------------------------------
// 2b) Small-M GEMM (fc1) and fc2 K-split
// ---------------------------------------------------------------------------
template <bool RELU>
__global__ __launch_bounds__(256) void gemm_tn(
    const float* __restrict__ Ag, int lda,
    const float* __restrict__ Wg, int ldw,
    const float* __restrict__ bias,
    float* __restrict__ Cg, int ldc,
    int M, int N, int K)
{
    __shared__ float As[16][65];
    __shared__ float Ws[16][65];
    int tid  = threadIdx.x;
    int row0 = blockIdx.y * 64;
    int col0 = blockIdx.x * 64;
    int lm = tid >> 2;
    int lk = (tid & 3) * 4;
    int ty = tid >> 4;
    int tx = tid & 15;
    float acc[4][4];
#pragma unroll
    for (int i = 0; i < 4; i++)
#pragma unroll
        for (int j = 0; j < 4; j++) acc[i][j] = 0.f;

    for (int k0 = 0; k0 < K; k0 += 16) {
        int r = row0 + lm;
        int cc = col0 + lm;
#pragma unroll
        for (int i = 0; i < 4; i++) {
            int k = k0 + lk + i;
            As[lk + i][lm] = (r < M && k < K) ? Ag[(size_t)r * lda + k] : 0.f;
            Ws[lk + i][lm] = (cc < N && k < K) ? Wg[(size_t)cc * ldw + k] : 0.f;
        }
        __syncthreads();
#pragma unroll
        for (int kk = 0; kk < 16; kk++) {
            float a[4], w[4];
#pragma unroll
            for (int i = 0; i < 4; i++) a[i] = As[kk][ty + 16 * i];
#pragma unroll
            for (int j = 0; j < 4; j++) w[j] = Ws[kk][tx + 16 * j];
#pragma unroll
            for (int i = 0; i < 4; i++)
#pragma unroll
                for (int j = 0; j < 4; j++)
                    acc[i][j] = fmaf(a[i], w[j], acc[i][j]);
        }
        __syncthreads();
    }

#pragma unroll
    for (int i = 0; i < 4; i++) {
        int r = row0 + ty + 16 * i;
        if (r >= M) continue;
#pragma unroll
        for (int j = 0; j < 4; j++) {
            int cc = col0 + tx + 16 * j;
            if (cc >= N) continue;
            float v = acc[i][j] + bias[cc];
            if (RELU) v = fmaxf(v, 0.f);
            Cg[(size_t)r * ldc + cc] = v;
        }
    }
}

__global__ __launch_bounds__(256) void fc2_part(
    const float* __restrict__ Ag,
    const float* __restrict__ Wg,
    float* __restrict__ Pout)
{
    __shared__ float As[16][65];
    __shared__ float Ws[16][65];
    int tid  = threadIdx.x;
    int col0 = blockIdx.x * 64;
    int kbeg = blockIdx.y * 1024;
    int lm = tid >> 2;
    int lk = (tid & 3) * 4;
    int ty = tid >> 4;
    int tx = tid & 15;
    float acc[4][4];
#pragma unroll
    for (int i = 0; i < 4; i++)
#pragma unroll
        for (int j = 0; j < 4; j++) acc[i][j] = 0.f;

    for (int k0 = kbeg; k0 < kbeg + 1024; k0 += 16) {
        int cc = col0 + lm;
#pragma unroll
        for (int i = 0; i < 4; i++) {
            int k = k0 + lk + i;
            As[lk + i][lm] = (lm < C) ? Ag[(size_t)lm * 4096 + k] : 0.f;
            Ws[lk + i][lm] = Wg[(size_t)cc * 4096 + k];
        }
        __syncthreads();
#pragma unroll
        for (int kk = 0; kk < 16; kk++) {
            float a[4], w[4];
#pragma unroll
            for (int i = 0; i < 4; i++) a[i] = As[kk][ty + 16 * i];
#pragma unroll
            for (int j = 0; j < 4; j++) w[j] = Ws[kk][tx + 16 * j];
#pragma unroll
            for (int i = 0; i < 4; i++)
#pragma unroll
                for (int j = 0; j < 4; j++)
                    acc[i][j] = fmaf(a[i], w[j], acc[i][j]);
        }
        __syncthreads();
    }

    float* base = Pout + (size_t)blockIdx.y * (64 * 512);
#pragma unroll
    for (int i = 0; i < 4; i++) {
        int r = ty + 16 * i;
        if (r >= C) continue;
#pragma unroll
        for (int j = 0; j < 4; j++) {
            int cc = col0 + tx + 16 * j;
            base[(size_t)r * 512 + cc] = acc[i][j];
        }
    }
}

__global__ __launch_bounds__(256) void fc2_reduce(
    const float* __restrict__ P, const float* __restrict__ bias,
    float* __restrict__ attr2)
{
    int idx = blockIdx.x * 256 + threadIdx.x;
    if (idx < C * 512) {
        int r = idx >> 9, cc = idx & 511;
        float v = bias[cc];
#pragma unroll
        for (int kc = 0; kc < 4; kc++)
            v += P[(size_t)kc * (64 * 512) + r * 512 + cc];
        attr2[idx] = fmaxf(v, 0.f);
    }
}

// ---------------------------------------------------------------------------
// 3) GRU recurrence (round-5 proven variant, byte-identical)
// ---------------------------------------------------------------------------
#define GRU_BLOCKS 128

__device__ __forceinline__ void grid_barrier()
{
    __syncthreads();
    if (threadIdx.x == 0) {
        __threadfence();
        unsigned g = ld_acq(&g_bar_gen);
        if (atomicAdd(&g_bar_count, 1) == GRU_BLOCKS - 1) {
            g_bar_count = 0;
            st_rel(&g_bar_gen, g + 1);
        } else {
            while (ld_acq(&g_bar_gen) == g) { __nanosleep(16); }
        }
    }
    __syncthreads();
}

__global__ __launch_bounds__(256) void gru_kernel(
    const float* __restrict__ GI,
    const float* __restrict__ whh_f, const float* __restrict__ whh_b,
    const float* __restrict__ bhh_f, const float* __restrict__ bhh_b,
    const float* __restrict__ bpack,
    const int*   __restrict__ count,
    float* __restrict__ feats)
{
    extern __shared__ float4 sm4[];
    float4* sW4 = sm4;
    float4* hS4 = sm4 + 12 * 65;

    int d  = blockIdx.x >> 6;
    int hc = blockIdx.x & 63;
    int tid = threadIdx.x;
    int b = tid >> 2;
    int u = tid & 3;
    int i = hc * 4 + u;

    const float* whh = d ? whh_b : whh_f;
    const float* bhh = d ? bhh_b : bhh_f;

    for (int t = tid; t < 12 * 64; t += 256) {
        int rr = t >> 6;
        int k4 = t & 63;
        int g  = rr >> 2, uu = rr & 3;
        int row = g * H + hc * 4 + uu;
        sW4[rr * 65 + k4] = ((const float4*)(whh + (size_t)row * H))[k4];
    }
    float br = bhh[i], bz = bhh[H + i], bn = bhh[2 * H + i];
    float ir0 = bpack[d * 768 + i];
    float iz0 = bpack[d * 768 + 256 + i];
    float in0 = bpack[d * 768 + 512 + i];
    int cnt_b = count[b];
    __syncthreads();

    float h = 0.f;

    for (int t = 0; t < T; t++) {
        float ar = 0.f, az = 0.f, an = 0.f;
        if (t > 0) {
            int p = t & 1;
            const float4* hp4 = (const float4*)(g_hbuf + p * (2 * B * H) + d * (B * H));
            for (int idx = tid; idx < B * (H / 4); idx += 256)
                hS4[(idx >> 6) * 65 + (idx & 63)] = __ldcg(&hp4[idx]);
            __syncthreads();

            const float4* hb = &hS4[b * 65];
            const float4* wr = &sW4[(0 + u) * 65];
            const float4* wz = &sW4[(4 + u) * 65];
            const float4* wn = &sW4[(8 + u) * 65];
#pragma unroll 16
            for (int k4 = 0; k4 < 64; k4++) {
                float4 hv = hb[k4];
                float4 a  = wr[k4];
                ar = fmaf(hv.x, a.x, fmaf(hv.y, a.y, fmaf(hv.z, a.z, fmaf(hv.w, a.w, ar))));
                float4 zz = wz[k4];
                az = fmaf(hv.x, zz.x, fmaf(hv.y, zz.y, fmaf(hv.z, zz.z, fmaf(hv.w, zz.w, az))));
                float4 nn = wn[k4];
                an = fmaf(hv.x, nn.x, fmaf(hv.y, nn.y, fmaf(hv.z, nn.z, fmaf(hv.w, nn.w, an))));
            }
        }

        int s = d ? (T - 1 - t) : t;
        float ir = ir0, iz = iz0, in_ = in0;
        if (s < cnt_b) {
            const float* gi = GI + ((size_t)b * T + s) * GI_W + d * 768;
            ir  = gi[i];
            iz  = gi[H + i];
            in_ = gi[2 * H + i];
        }

        float r = 1.f / (1.f + expf(-(ir + ar + br)));
        float z = 1.f / (1.f + expf(-(iz + az + bz)));
        float n = tanhf(in_ + r * (an + bn));
        h = (1.f - z) * n + z * h;

        feats[((size_t)b * T + s) * 512 + d * H + i] = h;
        if (t < T - 1) {
            g_hbuf[((t & 1) ^ 1) * (2 * B * H) + d * (B * H) + b * H + i] = h;
            grid_barrier();
        }
    }
}

// ---------------------------------------------------------------------------
// 4) Relation head, bf16 3-split tensor cores (bisect component under test)
// ---------------------------------------------------------------------------
__global__ __launch_bounds__(256, 2) void relation_bf16(
    const float* __restrict__ feats,
    const float* __restrict__ attr2,
    const __nv_bfloat16* __restrict__ w3hi,
    const __nv_bfloat16* __restrict__ w3lo,
    const float* __restrict__ b3,
    const float* __restrict__ w4,
    const float* __restrict__ b4,
    float* __restrict__ logits)
{
    __shared__ uint32_t Dh_s[64 * 12], Dl_s[64 * 12];
    __shared__ uint32_t Wh_s[256 * 12], Wl_s[256 * 12];
    __shared__ float aS[2 * 512];
    __shared__ float part[64][5];

    int c0 = blockIdx.x * 2;
    int b  = blockIdx.y;
    int tid  = threadIdx.x;
    int lane = tid & 31, warp = tid >> 5;
    int wm = warp >> 2, wn = warp & 3;
    int g  = lane >> 2, tg = lane & 3;

    for (int t = tid; t < 1024; t += 256)
        aS[t] = attr2[(size_t)(c0 + (t >> 9)) * 512 + (t & 511)];
    __syncthreads();

    float c[2][8][4];
#pragma unroll
    for (int mt = 0; mt < 2; mt++)
#pragma unroll
        for (int nt = 0; nt < 8; nt++)
#pragma unroll
            for (int r = 0; r < 4; r++) c[mt][nt][r] = 0.f;

    int dm = tid >> 2;                  // 0..63 (row of D tile)
    int dk = (tid & 3) * 4;             // k offset within 16
    int ds = dm & 31, dc = dm >> 5;
    const float* frow = feats + ((size_t)b * T + ds) * 512;
    const __nv_bfloat16* w3h_row = w3hi + (size_t)tid * 512;
    const __nv_bfloat16* w3l_row = w3lo + (size_t)tid * 512;

    for (int k0 = 0; k0 < 512; k0 += 16) {
        {
            float4 f = *(const float4*)(frow + k0 + dk);
            float4 a = *(const float4*)(aS + dc * 512 + k0 + dk);
            float d0 = f.x - a.x, d1 = f.y - a.y;
            float d2 = f.z - a.z, d3 = f.w - a.w;
            uint32_t h0, l0, h1, l1;
            bsplit2(d0 * d0, d1 * d1, h0, l0);
            bsplit2(d2 * d2, d3 * d3, h1, l1);
            int w = (tid & 3) * 2;
            Dh_s[dm * 12 + w]     = h0;
            Dh_s[dm * 12 + w + 1] = h1;
            Dl_s[dm * 12 + w]     = l0;
            Dl_s[dm * 12 + w + 1] = l1;
        }
        {
            uint4 wh0 = ((const uint4*)(w3h_row + k0))[0];
            uint4 wh1 = ((const uint4*)(w3h_row + k0))[1];
            uint4 wl0 = ((const uint4*)(w3l_row + k0))[0];
            uint4 wl1 = ((const uint4*)(w3l_row + k0))[1];
            *(uint4*)&Wh_s[tid * 12 + 0] = wh0;
            *(uint4*)&Wh_s[tid * 12 + 4] = wh1;
            *(uint4*)&Wl_s[tid * 12 + 0] = wl0;
            *(uint4*)&Wl_s[tid * 12 + 4] = wl1;
        }
        __syncthreads();

        uint32_t a_h[2][4], a_l[2][4];
#pragma unroll
        for (int mt = 0; mt < 2; mt++) {
            int m0 = wm * 32 + mt * 16;
            a_h[mt][0] = Dh_s[(m0 + g) * 12 + tg];
            a_h[mt][1] = Dh_s[(m0 + g + 8) * 12 + tg];
            a_h[mt][2] = Dh_s[(m0 + g) * 12 + tg + 4];
            a_h[mt][3] = Dh_s[(m0 + g + 8) * 12 + tg + 4];
            a_l[mt][0] = Dl_s[(m0 + g) * 12 + tg];
            a_l[mt][1] = Dl_s[(m0 + g + 8) * 12 + tg];
            a_l[mt][2] = Dl_s[(m0 + g) * 12 + tg + 4];
            a_l[mt][3] = Dl_s[(m0 + g + 8) * 12 + tg + 4];
        }
#pragma unroll
        for (int nt = 0; nt < 8; nt++) {
            int n0 = wn * 64 + nt * 8;
            uint32_t bh[2], bl[2];
            bh[0] = Wh_s[(n0 + g) * 12 + tg];
            bh[1] = Wh_s[(n0 + g) * 12 + tg + 4];
            bl[0] = Wl_s[(n0 + g) * 12 + tg];
            bl[1] = Wl_s[(n0 + g) * 12 + tg + 4];
#pragma unroll
            for (int mt = 0; mt < 2; mt++) {
                mma16(c[mt][nt], a_h[mt], bh);
                mma16(c[mt][nt], a_l[mt], bh);
                mma16(c[mt][nt], a_h[mt], bl);
            }
        }
        __syncthreads();
    }

    // relu + fc4 dot, reduce over the warp's 64 n-columns
    float rs[2][2] = {{0.f, 0.f}, {0.f, 0.f}};
#pragma unroll
    for (int nt = 0; nt < 8; nt++) {
        int col = wn * 64 + nt * 8 + 2 * tg;
        float w40 = w4[col], w41 = w4[col + 1];
        float b30 = b3[col], b31 = b3[col + 1];
#pragma unroll
        for (int mt = 0; mt < 2; mt++) {
            rs[mt][0] += fmaxf(c[mt][nt][0] + b30, 0.f) * w40
                       + fmaxf(c[mt][nt][1] + b31, 0.f) * w41;
            rs[mt][1] += fmaxf(c[mt][nt][2] + b30, 0.f) * w40
                       + fmaxf(c[mt][nt][3] + b31, 0.f) * w41;
        }
    }
#pragma unroll
    for (int mt = 0; mt < 2; mt++)
#pragma unroll
        for (int hf2 = 0; hf2 < 2; hf2++) {
            float v = rs[mt][hf2];
            v += __shfl_xor_sync(0xffffffffu, v, 1);
            v += __shfl_xor_sync(0xffffffffu, v, 2);
            if (tg == 0)
                part[wm * 32 + mt * 16 + g + hf2 * 8][wn] = v;
        }
    __syncthreads();
    if (tid < 64) {
        float s = b4[0] + part[tid][0] + part[tid][1] + part[tid][2] + part[tid][3];
        int cc = c0 + (tid >> 5), ss = tid & 31;
        logits[((size_t)b * C + cc) * T + ss] = s;
    }
}

// ---------------------------------------------------------------------------
// 5) Softmax over dim-0 per column, mean over columns
// ---------------------------------------------------------------------------
__global__ __launch_bounds__(256) void softmax_colreduce(
    const float* __restrict__ logits, float* __restrict__ cmax, float* __restrict__ csum)
{
    int t = blockIdx.x;
    int tid = threadIdx.x;
    __shared__ float red[256];
    float m = -1e30f;
    for (int i = tid; i < B * C; i += 256) m = fmaxf(m, logits[(size_t)i * T + t]);
    red[tid] = m; __syncthreads();
    for (int s = 128; s > 0; s >>= 1) {
        if (tid < s) red[tid] = fmaxf(red[tid], red[tid + s]);
        __syncthreads();
    }
    float mx = red[0];
    __syncthreads();
    float sum = 0.f;
    for (int i = tid; i < B * C; i += 256) sum += expf(logits[(size_t)i * T + t] - mx);
    red[tid] = sum; __syncthreads();
    for (int s = 128; s > 0; s >>= 1) {
        if (tid < s) red[tid] += red[tid + s];
        __syncthreads();
    }
    if (tid == 0) { cmax[t] = mx; csum[t] = red[0]; }
}

__global__ __launch_bounds__(256) void softmax_out(
    const float* __restrict__ logits, const float* __restrict__ cmax,
    const float* __restrict__ csum, float* __restrict__ out)
{
    __shared__ float mS[T], sS[T];
    int tid = threadIdx.x;
    if (tid < T) { mS[tid] = cmax[tid]; sS[tid] = csum[tid]; }
    __syncthreads();
    int i = blockIdx.x * 256 + tid;
    if (i < B * C) {
        float a = 0.f;
        const float* row = logits + (size_t)i * T;
#pragma unroll
        for (int t = 0; t < T; t++) a += expf(row[t] - mS[t]) / sS[t];
        out[i] = a * (1.f / (float)T);
    }
}

// ---------------------------------------------------------------------------
// Launch
// ---------------------------------------------------------------------------
extern "C" void kernel_launch(void* const* d_in, const int* in_sizes, int n_in,
                              void* d_out, int out_size)
{
    const float* batch_features  = (const float*)d_in[0];
    const float* batch_att       = (const float*)d_in[1];
    const float* batch_attrs     = (const float*)d_in[2];
    const float* fc1_w = (const float*)d_in[3];
    const float* fc1_b = (const float*)d_in[4];
    const float* fc2_w = (const float*)d_in[5];
    const float* fc2_b = (const float*)d_in[6];
    const float* fc3_w = (const float*)d_in[7];
    const float* fc3_b = (const float*)d_in[8];
    const float* fc4_w = (const float*)d_in[9];
    const float* fc4_b = (const float*)d_in[10];
    const float* gru_wih_f = (const float*)d_in[11];
    const float* gru_whh_f = (const float*)d_in[12];
    const float* gru_bih_f = (const float*)d_in[13];
    const float* gru_bhh_f = (const float*)d_in[14];
    const float* gru_wih_b = (const float*)d_in[15];
    const float* gru_whh_b = (const float*)d_in[16];
    const float* gru_bih_b = (const float*)d_in[17];
    const float* gru_bhh_b = (const float*)d_in[18];
    float* out = (float*)d_out;

    float* GI;     cudaGetSymbolAddress((void**)&GI,     g_GI);
    float* feats;  cudaGetSymbolAddress((void**)&feats,  g_feats);
    float* attr1;  cudaGetSymbolAddress((void**)&attr1,  g_attr1);
    float* attr2;  cudaGetSymbolAddress((void**)&attr2,  g_attr2);
    float* logits; cudaGetSymbolAddress((void**)&logits, g_logits);
    float* cmax;   cudaGetSymbolAddress((void**)&cmax,   g_cmax);
    float* csum;   cudaGetSymbolAddress((void**)&csum,   g_csum);
    float* wpack;  cudaGetSymbolAddress((void**)&wpack,  g_wih_pack);
    float* bpack;  cudaGetSymbolAddress((void**)&bpack,  g_bih_pack);
    __nv_bfloat16* w3hi; cudaGetSymbolAddress((void**)&w3hi, g_w3hi);
    __nv_bfloat16* w3lo; cudaGetSymbolAddress((void**)&w3lo, g_w3lo);
    float* fc2p;   cudaGetSymbolAddress((void**)&fc2p,   g_fc2part);
    int* rmin;     cudaGetSymbolAddress((void**)&rmin,   g_rmin);
    int* rmout;    cudaGetSymbolAddress((void**)&rmout,  g_rmout);
    int* cnt;      cudaGetSymbolAddress((void**)&cnt,    g_count);
    int* mnz;      cudaGetSymbolAddress((void**)&mnz,    g_mnz);

    build_maps<<<1, 64>>>(batch_att, rmin, rmout, cnt, mnz);
    pack_wih<<<(GI_W * D / 4 + 255) / 256, 256>>>(gru_wih_f, gru_wih_b,
                                                  gru_bih_f, gru_bih_b, wpack, bpack);
    split_w3_bf16<<<(256 * 512 / 2 + 255) / 256, 256>>>(fc3_w, w3hi, w3lo);

    // GI projection (tensor cores, 3xTF32, compacted rows — round-5 proven)
    {
        dim3 grid(GI_W / 64, (B * T) / 128);   // (24, 16); ~half exit early
        gemm_mma_gi<<<grid, 256>>>(batch_features, wpack, bpack, GI, rmin, rmout, mnz);
    }

    // GRU recurrence
    {
        int smem = (12 * 65 + 64 * 65) * (int)sizeof(float4);
        cudaFuncSetAttribute(gru_kernel, cudaFuncAttributeMaxDynamicSharedMemorySize, smem);
        gru_kernel<<<GRU_BLOCKS, 256, smem>>>(GI, gru_whh_f, gru_whh_b,
                                              gru_bhh_f, gru_bhh_b, bpack, cnt, feats);
    }

    // semantic net
    gemm_tn<true><<<dim3(4096 / 64, 1), 256>>>(batch_attrs, A_, fc1_w, A_, fc1_b,
                                               attr1, 4096, C, 4096, A_);
    fc2_part<<<dim3(8, 4), 256>>>(attr1, fc2_w, fc2p);
    fc2_reduce<<<(C * 512 + 255) / 256, 256>>>(fc2p, fc2_b, attr2);

    // relation head (bf16 3-split — the bisect component)
    relation_bf16<<<dim3(C / 2, B), 256>>>(feats, attr2, w3hi, w3lo,
                                           fc3_b, fc4_w, fc4_b, logits);

    softmax_colreduce<<<T, 256>>>(logits, cmax, csum);
    softmax_out<<<(B * C + 255) / 256, 256>>>(logits, cmax, csum, out);
}